// round 11
// baseline (speedup 1.0000x reference)
#include <cuda_runtime.h>
#include <cuda_fp16.h>
#include <cstdint>

#define NN   50000
#define EE   1600000
#define DINN 2000
#define BSCALE 4096.0f
#define BINV   (1.0f / 4096.0f)

// ---------------- device scratch (allocation-free contract) ----------------
__device__ float g_alpha1[2 * 500];
__device__ float g_bb1[2 * 500];
__device__ float g_alpha2[2 * 128];
__device__ float g_t2b[2 * 128];
__device__ float g_cmean[64];
__device__ float g_cprime[64];
__device__ float g_Wde2[2 * 128 * 64];   // 0.5 * alpha2[l] * (Wd @ Wg0)
__device__ float g_R[2 * 500 * 64];      // W2 @ Wde2
__device__ __half g_Bhi[64 * 4096];      // [e][m*2048+k] hi of 4096*M^T (pad zero)
__device__ __half g_Blo[64 * 4096];      // lo
__device__ float g_xw0[NN * 64];         // fp32 splitK accumulation target
__device__ float g_xw1[NN * 32];
__device__ float g_xw2[NN * 4];
__device__ float g_cs[NN];
__device__ float g_cd[NN];
__device__ int   g_degS[NN];             // zero at load; re-zeroed each call
__device__ int   g_degD[NN];
__device__ int   g_off[NN + 1];
__device__ int   g_epos[EE];
__device__ int   g_esrc[EE];
__device__ int   g_bsum[128];

// ---------------- PTX helpers ----------------
__device__ __forceinline__ uint32_t smem_u32(const void* p) {
    uint32_t a;
    asm("{ .reg .u64 t; cvta.to.shared.u64 t, %1; cvt.u32.u64 %0, t; }"
        : "=r"(a) : "l"(p));
    return a;
}

#define LDSM4(r, a) \
    asm volatile("ldmatrix.sync.aligned.m8n8.x4.shared.b16 {%0,%1,%2,%3}, [%4];" \
                 : "=r"((r)[0]), "=r"((r)[1]), "=r"((r)[2]), "=r"((r)[3]) : "r"(a))

#define MMA2(c, a, b0, b1) \
    asm volatile( \
        "mma.sync.aligned.m16n8k16.row.col.f32.f16.f16.f32 " \
        "{%0,%1,%2,%3}, {%4,%5,%6,%7}, {%8,%9}, {%0,%1,%2,%3};" \
        : "+f"((c)[0]), "+f"((c)[1]), "+f"((c)[2]), "+f"((c)[3]) \
        : "r"((a)[0]), "r"((a)[1]), "r"((a)[2]), "r"((a)[3]), \
          "r"(b0), "r"(b1))

#define CP_ASYNC16(dst, src) \
    asm volatile("cp.async.cg.shared.global [%0], [%1], 16;" \
                 :: "r"(dst), "l"(src) : "memory")
#define CP_COMMIT() asm volatile("cp.async.commit_group;" ::: "memory")
#define CP_WAIT0()  asm volatile("cp.async.wait_group 0;" ::: "memory")

// ---- A1: weight fold (blk 0) + zero xw0 (blks 1..200) -------------------------
__global__ __launch_bounds__(512) void k_foldW(
    const float* __restrict__ b1, const float* __restrict__ g1,
    const float* __restrict__ be1, const float* __restrict__ m1,
    const float* __restrict__ v1, const float* __restrict__ W2,
    const float* __restrict__ b2, const float* __restrict__ g2,
    const float* __restrict__ be2, const float* __restrict__ m2,
    const float* __restrict__ v2, const float* __restrict__ Wd,
    const float* __restrict__ bd, const float* __restrict__ Wg0) {
    int b = blockIdx.x;
    if (b >= 1) {
        float4 z = make_float4(0.f, 0.f, 0.f, 0.f);
        for (int i = (b - 1) * 512 + threadIdx.x; i < NN * 16; i += 200 * 512)
            reinterpret_cast<float4*>(g_xw0)[i] = z;
        return;
    }
    __shared__ float sWg0[64 * 64];
    int t = threadIdx.x;
    for (int i = t; i < 1000; i += 512) {
        float a = g1[i] * rsqrtf(v1[i] + 1e-5f);
        g_alpha1[i] = a;
        g_bb1[i] = (b1[i] - m1[i]) * a + be1[i];
    }
    for (int i = t; i < 256; i += 512)
        g_alpha2[i] = g2[i] * rsqrtf(v2[i] + 1e-5f);
    for (int i = t; i < 4096; i += 512) sWg0[i] = Wg0[i];
    __syncthreads();
    for (int i = t; i < 256; i += 512) {
        int mm = i >> 7, l = i & 127;
        float s = 0.f;
        for (int j = 0; j < 500; j++)
            s += g_bb1[mm * 500 + j] * W2[mm * 64000 + j * 128 + l];
        g_t2b[i] = (s + b2[i] - m2[i]) * g_alpha2[i] + be2[i];
    }
    for (int idx = t; idx < 16384; idx += 512) {
        int m = idx >> 13, rem = idx & 8191, l = rem >> 6, e = rem & 63;
        float s = 0.f;
        for (int d = 0; d < 64; d++)
            s += Wd[m * 8192 + l * 64 + d] * sWg0[d * 64 + e];
        g_Wde2[idx] = 0.5f * g_alpha2[m * 128 + l] * s;
    }
    __syncthreads();
    for (int d = t; d < 64; d += 512) {
        float s = 0.f;
        for (int mm = 0; mm < 2; mm++) {
            float sm = bd[mm * 64 + d];
            for (int l = 0; l < 128; l++)
                sm += g_t2b[mm * 128 + l] * Wd[mm * 8192 + l * 64 + d];
            s += sm;
        }
        g_cmean[d] = 0.5f * s;
    }
    __syncthreads();
    for (int e = t; e < 64; e += 512) {
        float s = 0.f;
        for (int d = 0; d < 64; d++) s += g_cmean[d] * sWg0[d * 64 + e];
        g_cprime[e] = s;
    }
}

// ---- A2: R[m][j][e] = sum_l W2[m][j][l] * Wde2[m][l][e] -----------------------
__global__ __launch_bounds__(512) void k_R(const float* __restrict__ W2) {
    int b = blockIdx.x, t = threadIdx.x;
    int m = b / 63, j0 = (b % 63) * 8;
    int jr = t >> 6, e = t & 63;
    int j = j0 + jr;
    if (j >= 500) return;
    const float* w2row = W2 + m * 64000 + j * 128;
    const float* wde = g_Wde2 + m * 8192 + e;
    float acc = 0.f;
#pragma unroll 4
    for (int l = 0; l < 128; l++)
        acc = fmaf(__ldg(&w2row[l]), __ldg(&wde[l * 64]), acc);
    g_R[m * 32000 + j * 64 + e] = acc;
}

// ---- A3: M = (W1*alpha1) @ R -> fp16 hi/lo (scaled x4096) ---------------------
__global__ __launch_bounds__(512) void k_MB(const float* __restrict__ W1) {
    __shared__ float sA[8][500];
    __shared__ float red[7][8][64];
    int b = blockIdx.x, t = threadIdx.x;
    int m = b / 250, i0 = (b % 250) * 8;
    for (int idx = t; idx < 4000; idx += 512) {
        int r = idx / 500, j = idx - r * 500;
        sA[r][j] = W1[m * 1000000 + (i0 + r) * 500 + j] * g_alpha1[m * 500 + j];
    }
    __syncthreads();
    int e = t & 63, jp = t >> 6;
    float acc[8] = {0, 0, 0, 0, 0, 0, 0, 0};
    for (int j = jp; j < 500; j += 8) {
        float w = g_R[m * 32000 + j * 64 + e];
#pragma unroll
        for (int r = 0; r < 8; r++) acc[r] += sA[r][j] * w;
    }
    if (jp > 0) {
#pragma unroll
        for (int r = 0; r < 8; r++) red[jp - 1][r][e] = acc[r];
    }
    __syncthreads();
    if (jp == 0) {
#pragma unroll
        for (int r = 0; r < 8; r++) {
            float v = acc[r];
#pragma unroll
            for (int p = 0; p < 7; p++) v += red[p][r][e];
            v *= BSCALE;
            __half hi = __float2half_rn(v);
            g_Bhi[e * 4096 + m * 2048 + i0 + r] = hi;
            g_Blo[e * 4096 + m * 2048 + i0 + r] = __float2half_rn(v - __half2float(hi));
        }
    }
}

// ---- A4: 64x64-tile HMMA GEMM (splitK=4): xw0 += partials ---------------------
#define SM_A 0                       // 2 buf x 8192 (fp16 A-hi, 64 rows)
#define SM_B 16384                   // 2 buf x (8192 hi + 8192 lo)
#define SMEM_BYTES 49152

__global__ __launch_bounds__(128, 4) void k_gemm_hmma(const float* __restrict__ h) {
    int b = blockIdx.x;
    int tid = threadIdx.x;
    extern __shared__ __align__(1024) char smem[];
    uint32_t sbase = smem_u32(smem);
    int lane = tid & 31, wid = tid >> 5;
    int wm = wid >> 1, wn = wid & 1;
    int bx = b % 782, by = b / 782;
    int row0 = bx * 64;
    int m = by >> 1, kh = by & 1;
    const float* hb = h + (long long)m * NN * DINN;
    const __half* bhi = g_Bhi + m * 2048 + kh * 1024;
    const __half* blo = g_Blo + m * 2048 + kh * 1024;
    int kbase = kh * 1024;

    uint32_t swz = (uint32_t)(lane & 7) << 4;
    uint32_t aoff = (uint32_t)(wm * 32 + (lane & 15)) * 128;
    uint32_t acolsel = (uint32_t)(lane >> 4) << 4;
    uint32_t boff = (uint32_t)(wn * 32 + lane) * 128;

    float c_[2][4][4];
#pragma unroll
    for (int mt = 0; mt < 2; mt++)
#pragma unroll
        for (int nt = 0; nt < 4; nt++)
#pragma unroll
            for (int q = 0; q < 4; q++) c_[mt][nt][q] = 0.f;

    float4 va[8];

    auto ldgA = [&](int c) {
        int k0 = kbase + c * 64;
        const float* base = hb + (long long)row0 * DINN + k0;
        if (row0 + 64 <= NN && k0 + 64 <= 2000) {
#pragma unroll
            for (int i = 0; i < 8; i++) {
                int idx = tid + 128 * i;
                int r = idx >> 4, cg = idx & 15;
                va[i] = *reinterpret_cast<const float4*>(base + (long long)r * DINN + cg * 4);
            }
        } else {
#pragma unroll
            for (int i = 0; i < 8; i++) {
                int idx = tid + 128 * i;
                int r = idx >> 4, cg = idx & 15;
                if (row0 + r < NN && k0 + cg * 4 + 3 < 2000)
                    va[i] = *reinterpret_cast<const float4*>(base + (long long)r * DINN + cg * 4);
                else
                    va[i] = make_float4(0.f, 0.f, 0.f, 0.f);
            }
        }
    };

    auto cpB = [&](int c, int buf) {
        int k0 = c * 64;
        uint32_t bH = sbase + SM_B + buf * 16384, bL = bH + 8192;
#pragma unroll
        for (int i = 0; i < 4; i++) {
            int idx = tid + 128 * i;
            int r = idx >> 3, cg = idx & 7;
            uint32_t off = (uint32_t)r * 128 +
                           (((uint32_t)cg * 16) ^ (((uint32_t)r & 7) << 4));
            CP_ASYNC16(bH + off, bhi + r * 4096 + k0 + cg * 8);
            CP_ASYNC16(bL + off, blo + r * 4096 + k0 + cg * 8);
        }
        CP_COMMIT();
    };

    auto stsA = [&](int buf) {
        uint32_t aH = SM_A + buf * 8192;
#pragma unroll
        for (int i = 0; i < 8; i++) {
            int idx = tid + 128 * i;
            int r = idx >> 4, cg = idx & 15;
            float4 v = va[i];
            __half2 h01 = __float22half2_rn(make_float2(v.x, v.y));
            __half2 h23 = __float22half2_rn(make_float2(v.z, v.w));
            uint32_t off = (uint32_t)r * 128 +
                           (((uint32_t)cg * 8) ^ (((uint32_t)r & 7) << 4));
            *reinterpret_cast<uint2*>(smem + aH + off) =
                make_uint2(*reinterpret_cast<uint32_t*>(&h01),
                           *reinterpret_cast<uint32_t*>(&h23));
        }
    };

    auto compute = [&](int buf) {
        uint32_t aH = sbase + SM_A + buf * 8192;
        uint32_t bH = sbase + SM_B + buf * 16384, bL = bH + 8192;
#pragma unroll
        for (int ks = 0; ks < 4; ks++) {
            uint32_t kb = (uint32_t)ks * 32;
            uint32_t aF[2][4];
            uint32_t b0h[4], b1h[4], b0l[4], b1l[4];
#pragma unroll
            for (int mt = 0; mt < 2; mt++) {
                uint32_t adr = aoff + (uint32_t)mt * 2048 + ((kb + acolsel) ^ swz);
                LDSM4(aF[mt], aH + adr);
            }
            LDSM4(b0h, bH + boff + ((kb + 0) ^ swz));
            LDSM4(b1h, bH + boff + ((kb + 16) ^ swz));
            LDSM4(b0l, bL + boff + ((kb + 0) ^ swz));
            LDSM4(b1l, bL + boff + ((kb + 16) ^ swz));
#pragma unroll
            for (int mt = 0; mt < 2; mt++)
#pragma unroll
                for (int nt = 0; nt < 4; nt++) {
                    MMA2(c_[mt][nt], aF[mt], b0h[nt], b1h[nt]);
                    MMA2(c_[mt][nt], aF[mt], b0l[nt], b1l[nt]);
                }
        }
    };

    ldgA(0);
    cpB(0, 0);
    stsA(0);
    CP_WAIT0();
    __syncthreads();

    for (int c = 0; c < 16; c++) {
        int buf = c & 1;
        bool more = (c + 1 < 16);
        if (more) {
            ldgA(c + 1);
            cpB(c + 1, buf ^ 1);
        }
        compute(buf);
        if (more) {
            stsA(buf ^ 1);
            CP_WAIT0();
            __syncthreads();
        }
    }

    int g = lane >> 2;
    int base_r = row0 + wm * 32 + g;
    int col0 = wn * 32 + (lane & 3) * 2;
#pragma unroll
    for (int mt = 0; mt < 2; mt++) {
#pragma unroll
        for (int rr = 0; rr < 2; rr++) {
            int gr = base_r + mt * 16 + rr * 8;
            if (gr < NN) {
#pragma unroll
                for (int nt = 0; nt < 4; nt++) {
                    int col = col0 + nt * 8;
                    float2 v;
                    v.x = c_[mt][nt][rr * 2 + 0] * BINV;
                    v.y = c_[mt][nt][rr * 2 + 1] * BINV;
                    atomicAdd(reinterpret_cast<float2*>(&g_xw0[gr * 64 + col]), v);
                }
            }
        }
    }
}

// ---- B1: degrees + edge positions ---------------------------------------------
__global__ __launch_bounds__(512) void k_foldE(const int* __restrict__ src,
                                               const int* __restrict__ dst) {
    int e = blockIdx.x * 512 + threadIdx.x;
    if (e < EE) {
        g_epos[e] = atomicAdd(&g_degD[dst[e]], 1);
        atomicAdd(&g_degS[src[e]], 1);
    }
}

// ---- B2: block sums of degD ---------------------------------------------------
__global__ __launch_bounds__(512) void k_scanA() {
    __shared__ int sw[16];
    int t = threadIdx.x;
    int i = blockIdx.x * 512 + t;
    int v = (i < NN) ? g_degD[i] : 0;
#pragma unroll
    for (int o = 16; o >= 1; o >>= 1) v += __shfl_xor_sync(0xFFFFFFFFu, v, o);
    if ((t & 31) == 0) sw[t >> 5] = v;
    __syncthreads();
    if (t < 32) {
        int x = (t < 16) ? sw[t] : 0;
#pragma unroll
        for (int o = 8; o >= 1; o >>= 1) x += __shfl_xor_sync(0xFFFFFFFFu, x, o);
        if (t == 0) g_bsum[blockIdx.x] = x;
    }
}

// ---- B3: CSR offsets + cs/cd --------------------------------------------------
__global__ __launch_bounds__(512) void k_scanC() {
    __shared__ int sd[512];
    __shared__ int sboff;
    int bid = blockIdx.x, t = threadIdx.x;
    int i = bid * 512 + t;
    int v = (i < NN) ? g_degD[i] : 0;
    sd[t] = v;
    __syncthreads();
    for (int s = 1; s < 512; s <<= 1) {
        int x = (t >= s) ? sd[t - s] : 0;
        __syncthreads();
        sd[t] += x;
        __syncthreads();
    }
    if (t == 0) {
        int run = 0;
        for (int j = 0; j < bid; j++) run += g_bsum[j];
        sboff = run;
        if (bid == 0) g_off[NN] = EE;
    }
    __syncthreads();
    if (i < NN) {
        g_off[i] = sboff + sd[t] - v;
        g_cs[i] = rsqrtf(fmaxf((float)g_degS[i], 1.0f));
        g_cd[i] = rsqrtf(fmaxf((float)v, 1.0f));
    }
}

// ---- B4: CSR fill (blks 0..3124) + degree rezero (blks 3125..3222) ------------
__global__ __launch_bounds__(512) void k_fill(const int* __restrict__ src,
                                              const int* __restrict__ dst) {
    int b = blockIdx.x;
    if (b < 3125) {
        int e = b * 512 + threadIdx.x;
        g_esrc[g_off[dst[e]] + g_epos[e]] = src[e];
        return;
    }
    int i = (b - 3125) * 512 + threadIdx.x;
    if (i < NN) { g_degS[i] = 0; g_degD[i] = 0; }
}

// ---- J1: gather cs*(xw0+c') + relu/bias/norm + GEMV 64->32 -> xw1 -------------
__global__ __launch_bounds__(256) void k_g64(const float* __restrict__ bg0,
                                             const float* __restrict__ Wg1) {
    __shared__ float sW[64 * 32];
    __shared__ float sb[64];
    __shared__ float sc[64];
    int t = threadIdx.x;
    for (int i = t; i < 2048; i += 256) sW[i] = Wg1[i];
    if (t < 64) { sb[t] = bg0[t]; sc[t] = g_cprime[t]; }
    __syncthreads();
    int wid = t >> 5, lane = t & 31;
    int n = blockIdx.x * 8 + wid;
    if (n >= NN) return;
    int beg = g_off[n], end = g_off[n + 1];
    int half = lane >> 4, l16 = lane & 15;
    float4 acc = make_float4(0.f, 0.f, 0.f, 0.f);
    float scs = 0.f;
    int i = beg + half;
    while (i + 6 < end) {
        int s0 = __ldg(&g_esrc[i]), s1 = __ldg(&g_esrc[i + 2]);
        int s2 = __ldg(&g_esrc[i + 4]), s3 = __ldg(&g_esrc[i + 6]);
        float cs0 = __ldg(&g_cs[s0]), cs1 = __ldg(&g_cs[s1]);
        float cs2 = __ldg(&g_cs[s2]), cs3 = __ldg(&g_cs[s3]);
        float4 v0 = __ldg(reinterpret_cast<const float4*>(&g_xw0[s0 * 64 + l16 * 4]));
        float4 v1 = __ldg(reinterpret_cast<const float4*>(&g_xw0[s1 * 64 + l16 * 4]));
        float4 v2 = __ldg(reinterpret_cast<const float4*>(&g_xw0[s2 * 64 + l16 * 4]));
        float4 v3 = __ldg(reinterpret_cast<const float4*>(&g_xw0[s3 * 64 + l16 * 4]));
        acc.x += v0.x * cs0 + v1.x * cs1 + v2.x * cs2 + v3.x * cs3;
        acc.y += v0.y * cs0 + v1.y * cs1 + v2.y * cs2 + v3.y * cs3;
        acc.z += v0.z * cs0 + v1.z * cs1 + v2.z * cs2 + v3.z * cs3;
        acc.w += v0.w * cs0 + v1.w * cs1 + v2.w * cs2 + v3.w * cs3;
        scs += cs0 + cs1 + cs2 + cs3;
        i += 8;
    }
    while (i < end) {
        int s = __ldg(&g_esrc[i]);
        float cs0 = __ldg(&g_cs[s]);
        float4 v = __ldg(reinterpret_cast<const float4*>(&g_xw0[s * 64 + l16 * 4]));
        acc.x += v.x * cs0; acc.y += v.y * cs0; acc.z += v.z * cs0; acc.w += v.w * cs0;
        scs += cs0;
        i += 2;
    }
    acc.x += __shfl_xor_sync(0xFFFFFFFFu, acc.x, 16);
    acc.y += __shfl_xor_sync(0xFFFFFFFFu, acc.y, 16);
    acc.z += __shfl_xor_sync(0xFFFFFFFFu, acc.z, 16);
    acc.w += __shfl_xor_sync(0xFFFFFFFFu, acc.w, 16);
    scs   += __shfl_xor_sync(0xFFFFFFFFu, scs, 16);
    float cdv = g_cd[n], csv = g_cs[n];
    float val[4];
    val[0] = fmaxf(fmaf(fmaf(sc[l16 * 4 + 0], scs, acc.x), cdv, sb[l16 * 4 + 0]), 0.f) * csv;
    val[1] = fmaxf(fmaf(fmaf(sc[l16 * 4 + 1], scs, acc.y), cdv, sb[l16 * 4 + 1]), 0.f) * csv;
    val[2] = fmaxf(fmaf(fmaf(sc[l16 * 4 + 2], scs, acc.z), cdv, sb[l16 * 4 + 2]), 0.f) * csv;
    val[3] = fmaxf(fmaf(fmaf(sc[l16 * 4 + 3], scs, acc.w), cdv, sb[l16 * 4 + 3]), 0.f) * csv;
    float o = 0.f;
#pragma unroll
    for (int d = 0; d < 64; d++) {
        float v = __shfl_sync(0xFFFFFFFFu, val[d & 3], d >> 2);
        o = fmaf(v, sW[d * 32 + lane], o);
    }
    g_xw1[n * 32 + lane] = o;
}

// ---- J2: gather xw1 + relu/bias/norm + GEMV 32->4 -> xw2 ----------------------
__global__ __launch_bounds__(256) void k_g32(const float* __restrict__ bg1,
                                             const float* __restrict__ Wg2) {
    __shared__ float sW[32 * 4];
    __shared__ float sb[32];
    int t = threadIdx.x;
    if (t < 128) sW[t] = Wg2[t];
    if (t < 32) sb[t] = bg1[t];
    __syncthreads();
    int wid = t >> 5, lane = t & 31;
    int n = blockIdx.x * 8 + wid;
    if (n >= NN) return;
    int beg = g_off[n], end = g_off[n + 1];
    int q = lane >> 3, l8 = lane & 7;
    float4 acc = make_float4(0.f, 0.f, 0.f, 0.f);
    int i = beg + q;
    while (i + 12 < end) {
        int s0 = __ldg(&g_esrc[i]), s1 = __ldg(&g_esrc[i + 4]);
        int s2 = __ldg(&g_esrc[i + 8]), s3 = __ldg(&g_esrc[i + 12]);
        float4 v0 = __ldg(reinterpret_cast<const float4*>(&g_xw1[s0 * 32 + l8 * 4]));
        float4 v1 = __ldg(reinterpret_cast<const float4*>(&g_xw1[s1 * 32 + l8 * 4]));
        float4 v2 = __ldg(reinterpret_cast<const float4*>(&g_xw1[s2 * 32 + l8 * 4]));
        float4 v3 = __ldg(reinterpret_cast<const float4*>(&g_xw1[s3 * 32 + l8 * 4]));
        acc.x += v0.x + v1.x + v2.x + v3.x;
        acc.y += v0.y + v1.y + v2.y + v3.y;
        acc.z += v0.z + v1.z + v2.z + v3.z;
        acc.w += v0.w + v1.w + v2.w + v3.w;
        i += 16;
    }
    while (i < end) {
        int s = __ldg(&g_esrc[i]);
        float4 v = __ldg(reinterpret_cast<const float4*>(&g_xw1[s * 32 + l8 * 4]));
        acc.x += v.x; acc.y += v.y; acc.z += v.z; acc.w += v.w;
        i += 4;
    }
    acc.x += __shfl_xor_sync(0xFFFFFFFFu, acc.x, 8);
    acc.y += __shfl_xor_sync(0xFFFFFFFFu, acc.y, 8);
    acc.z += __shfl_xor_sync(0xFFFFFFFFu, acc.z, 8);
    acc.w += __shfl_xor_sync(0xFFFFFFFFu, acc.w, 8);
    acc.x += __shfl_xor_sync(0xFFFFFFFFu, acc.x, 16);
    acc.y += __shfl_xor_sync(0xFFFFFFFFu, acc.y, 16);
    acc.z += __shfl_xor_sync(0xFFFFFFFFu, acc.z, 16);
    acc.w += __shfl_xor_sync(0xFFFFFFFFu, acc.w, 16);
    float cdv = g_cd[n], csv = g_cs[n];
    float val[4];
    val[0] = fmaxf(fmaf(acc.x, cdv, sb[l8 * 4 + 0]), 0.f) * csv;
    val[1] = fmaxf(fmaf(acc.y, cdv, sb[l8 * 4 + 1]), 0.f) * csv;
    val[2] = fmaxf(fmaf(acc.z, cdv, sb[l8 * 4 + 2]), 0.f) * csv;
    val[3] = fmaxf(fmaf(acc.w, cdv, sb[l8 * 4 + 3]), 0.f) * csv;
    float o = 0.f;
#pragma unroll
    for (int d = 0; d < 32; d++) {
        float v = __shfl_sync(0xFFFFFFFFu, val[d & 3], d >> 2);
        o = fmaf(v, sW[d * 4 + (lane & 3)], o);
    }
    if (lane < 4) g_xw2[n * 4 + lane] = o;
}

// ---- J3: gather xw2 + bias -> out ---------------------------------------------
__global__ __launch_bounds__(256) void k_g4(const float* __restrict__ bg2,
                                            float* __restrict__ out) {
    int t = threadIdx.x;
    int wid = t >> 5, lane = t & 31;
    int n = blockIdx.x * 8 + wid;
    if (n >= NN) return;
    int beg = g_off[n], end = g_off[n + 1];
    float4 acc = make_float4(0.f, 0.f, 0.f, 0.f);
    for (int i = beg + lane; i < end; i += 32) {
        int s = __ldg(&g_esrc[i]);
        float4 v = __ldg(reinterpret_cast<const float4*>(&g_xw2[s * 4]));
        acc.x += v.x; acc.y += v.y; acc.z += v.z; acc.w += v.w;
    }
#pragma unroll
    for (int off = 16; off >= 1; off >>= 1) {
        acc.x += __shfl_xor_sync(0xFFFFFFFFu, acc.x, off);
        acc.y += __shfl_xor_sync(0xFFFFFFFFu, acc.y, off);
        acc.z += __shfl_xor_sync(0xFFFFFFFFu, acc.z, off);
        acc.w += __shfl_xor_sync(0xFFFFFFFFu, acc.w, off);
    }
    if (lane == 0) {
        float cdv = g_cd[n];
        float4 o;
        o.x = fmaf(acc.x, cdv, bg2[0]);
        o.y = fmaf(acc.y, cdv, bg2[1]);
        o.z = fmaf(acc.z, cdv, bg2[2]);
        o.w = fmaf(acc.w, cdv, bg2[3]);
        *reinterpret_cast<float4*>(&out[n * 4]) = o;
    }
}

// ---------------- launch (fork-join capture: graph chain ∥ GEMM chain) ---------
extern "C" void kernel_launch(void* const* d_in, const int* in_sizes, int n_in,
                              void* d_out, int out_size) {
    const float* h   = (const float*)d_in[0];
    const int*   src = (const int*)d_in[1];
    const int*   dst = (const int*)d_in[2];
    const float* W1  = (const float*)d_in[3];
    const float* b1  = (const float*)d_in[4];
    const float* g1  = (const float*)d_in[5];
    const float* be1 = (const float*)d_in[6];
    const float* m1  = (const float*)d_in[7];
    const float* v1  = (const float*)d_in[8];
    const float* W2  = (const float*)d_in[9];
    const float* b2  = (const float*)d_in[10];
    const float* g2  = (const float*)d_in[11];
    const float* be2 = (const float*)d_in[12];
    const float* m2  = (const float*)d_in[13];
    const float* v2  = (const float*)d_in[14];
    const float* Wd  = (const float*)d_in[15];
    const float* bd  = (const float*)d_in[16];
    const float* Wg0 = (const float*)d_in[17];
    const float* bg0 = (const float*)d_in[18];
    const float* Wg1 = (const float*)d_in[19];
    const float* bg1 = (const float*)d_in[20];
    const float* Wg2 = (const float*)d_in[21];
    const float* bg2 = (const float*)d_in[22];
    float* out = (float*)d_out;

    static cudaStream_t s2 = nullptr;
    static cudaEvent_t ev0 = nullptr, evB = nullptr;
    if (s2 == nullptr) {
        cudaStreamCreateWithFlags(&s2, cudaStreamNonBlocking);
        cudaEventCreateWithFlags(&ev0, cudaEventDisableTiming);
        cudaEventCreateWithFlags(&evB, cudaEventDisableTiming);
        cudaFuncSetAttribute(k_gemm_hmma,
                             cudaFuncAttributeMaxDynamicSharedMemorySize, SMEM_BYTES);
    }

    // fork point: side chain B waits on entry event
    cudaEventRecord(ev0, 0);

    // chain A (capture stream): weight fold -> R -> MB -> GEMM
    k_foldW<<<201, 512>>>(b1, g1, be1, m1, v1, W2, b2, g2,
                          be2, m2, v2, Wd, bd, Wg0);               // 1
    k_R<<<126, 512>>>(W2);                                         // 2
    k_MB<<<500, 512>>>(W1);                                        // 3
    k_gemm_hmma<<<3128, 128, SMEM_BYTES>>>(h);                     // 4 <- ncu

    // chain B (side stream): degrees -> scan -> CSR fill (+ rezero)
    cudaStreamWaitEvent(s2, ev0, 0);
    k_foldE<<<3125, 512, 0, s2>>>(src, dst);                       // 5
    k_scanA<<<98, 512, 0, s2>>>();                                 // 6
    k_scanC<<<98, 512, 0, s2>>>();                                 // 7
    k_fill<<<3223, 512, 0, s2>>>(src, dst);                        // 8
    cudaEventRecord(evB, s2);

    // join: gathers need both chains
    cudaStreamWaitEvent(0, evB, 0);
    k_g64<<<(NN + 7) / 8, 256>>>(bg0, Wg1);                        // 9
    k_g32<<<(NN + 7) / 8, 256>>>(bg1, Wg2);                        // 10
    k_g4<<<(NN + 7) / 8, 256>>>(bg2, out);                         // 11
}

// round 12
// speedup vs baseline: 1.1009x; 1.1009x over previous
#include <cuda_runtime.h>
#include <cuda_fp16.h>
#include <cstdint>

#define NN   50000
#define EE   1600000
#define DINN 2000
#define BSCALE 4096.0f
#define BINV   (1.0f / 4096.0f)

// ---------------- device scratch (allocation-free contract) ----------------
__device__ float g_alpha1[2 * 500];
__device__ float g_bb1[2 * 500];
__device__ float g_alpha2[2 * 128];
__device__ float g_t2b[2 * 128];
__device__ float g_cmean[64];
__device__ float g_cprime[64];
__device__ float g_Wde2[2 * 128 * 64];   // 0.5 * alpha2[l] * (Wd @ Wg0)
__device__ float g_R[2 * 500 * 64];      // W2 @ Wde2
__device__ __half g_Bhi[64 * 4096];      // [e][m*2048+k] fp16 of 4096*M^T (pad zero)
__device__ float g_xw0[NN * 64];         // fp32 splitK accumulation target
__device__ float g_xw1[NN * 32];
__device__ float g_xw2[NN * 4];
__device__ float g_cs[NN];
__device__ float g_cd[NN];
__device__ int   g_degS[NN];             // zero at load; re-zeroed each call
__device__ int   g_degD[NN];
__device__ int   g_off[NN + 1];
__device__ int   g_epos[EE];
__device__ int   g_esrc[EE];
__device__ int   g_bsum[128];

// ---------------- PTX helpers ----------------
__device__ __forceinline__ uint32_t smem_u32(const void* p) {
    uint32_t a;
    asm("{ .reg .u64 t; cvta.to.shared.u64 t, %1; cvt.u32.u64 %0, t; }"
        : "=r"(a) : "l"(p));
    return a;
}

#define LDSM4(r, a) \
    asm volatile("ldmatrix.sync.aligned.m8n8.x4.shared.b16 {%0,%1,%2,%3}, [%4];" \
                 : "=r"((r)[0]), "=r"((r)[1]), "=r"((r)[2]), "=r"((r)[3]) : "r"(a))

#define MMA2(c, a, b0, b1) \
    asm volatile( \
        "mma.sync.aligned.m16n8k16.row.col.f32.f16.f16.f32 " \
        "{%0,%1,%2,%3}, {%4,%5,%6,%7}, {%8,%9}, {%0,%1,%2,%3};" \
        : "+f"((c)[0]), "+f"((c)[1]), "+f"((c)[2]), "+f"((c)[3]) \
        : "r"((a)[0]), "r"((a)[1]), "r"((a)[2]), "r"((a)[3]), \
          "r"(b0), "r"(b1))

#define CP_ASYNC16(dst, src) \
    asm volatile("cp.async.cg.shared.global [%0], [%1], 16;" \
                 :: "r"(dst), "l"(src) : "memory")
#define CP_COMMIT() asm volatile("cp.async.commit_group;" ::: "memory")
#define CP_WAIT0()  asm volatile("cp.async.wait_group 0;" ::: "memory")

// ---- L1: fold (blk 0) + degrees/epos (blk 1..3125) + zero xw0 (rest) ----------
__global__ __launch_bounds__(512) void k_fold(
    const int* __restrict__ src, const int* __restrict__ dst,
    const float* __restrict__ b1, const float* __restrict__ g1,
    const float* __restrict__ be1, const float* __restrict__ m1,
    const float* __restrict__ v1, const float* __restrict__ W2,
    const float* __restrict__ b2, const float* __restrict__ g2,
    const float* __restrict__ be2, const float* __restrict__ m2,
    const float* __restrict__ v2, const float* __restrict__ Wd,
    const float* __restrict__ bd, const float* __restrict__ Wg0) {
    int b = blockIdx.x;
    if (b >= 1 && b <= 3125) {
        int e = (b - 1) * 512 + threadIdx.x;
        if (e < EE) {
            g_epos[e] = atomicAdd(&g_degD[dst[e]], 1);
            atomicAdd(&g_degS[src[e]], 1);
        }
        return;
    }
    if (b > 3125) {
        float4 z = make_float4(0.f, 0.f, 0.f, 0.f);
        for (int i = (b - 3126) * 512 + threadIdx.x; i < NN * 16; i += 200 * 512)
            reinterpret_cast<float4*>(g_xw0)[i] = z;
        return;
    }
    __shared__ float sWg0[64 * 64];
    int t = threadIdx.x;
    for (int i = t; i < 1000; i += 512) {
        float a = g1[i] * rsqrtf(v1[i] + 1e-5f);
        g_alpha1[i] = a;
        g_bb1[i] = (b1[i] - m1[i]) * a + be1[i];
    }
    for (int i = t; i < 256; i += 512)
        g_alpha2[i] = g2[i] * rsqrtf(v2[i] + 1e-5f);
    for (int i = t; i < 4096; i += 512) sWg0[i] = Wg0[i];
    __syncthreads();
    for (int i = t; i < 256; i += 512) {
        int mm = i >> 7, l = i & 127;
        float s = 0.f;
        for (int j = 0; j < 500; j++)
            s += g_bb1[mm * 500 + j] * W2[mm * 64000 + j * 128 + l];
        g_t2b[i] = (s + b2[i] - m2[i]) * g_alpha2[i] + be2[i];
    }
    for (int idx = t; idx < 16384; idx += 512) {
        int m = idx >> 13, rem = idx & 8191, l = rem >> 6, e = rem & 63;
        float s = 0.f;
        for (int d = 0; d < 64; d++)
            s += Wd[m * 8192 + l * 64 + d] * sWg0[d * 64 + e];
        g_Wde2[idx] = 0.5f * g_alpha2[m * 128 + l] * s;
    }
    __syncthreads();
    for (int d = t; d < 64; d += 512) {
        float s = 0.f;
        for (int mm = 0; mm < 2; mm++) {
            float sm = bd[mm * 64 + d];
            for (int l = 0; l < 128; l++)
                sm += g_t2b[mm * 128 + l] * Wd[mm * 8192 + l * 64 + d];
            s += sm;
        }
        g_cmean[d] = 0.5f * s;
    }
    __syncthreads();
    for (int e = t; e < 64; e += 512) {
        float s = 0.f;
        for (int d = 0; d < 64; d++) s += g_cmean[d] * sWg0[d * 64 + e];
        g_cprime[e] = s;
    }
}

// ---- L2: R (blocks 0..125, all 512 thr) + scanA (blocks 126..223) -------------
__global__ __launch_bounds__(512) void k_Rscan(const float* __restrict__ W2) {
    int b = blockIdx.x;
    int t = threadIdx.x;
    if (b < 126) {
        int m = b / 63, j0 = (b % 63) * 8;
        int jr = t >> 6, e = t & 63;
        int j = j0 + jr;
        if (j >= 500) return;
        const float* w2row = W2 + m * 64000 + j * 128;
        const float* wde = g_Wde2 + m * 8192 + e;
        float acc = 0.f;
#pragma unroll 4
        for (int l = 0; l < 128; l++)
            acc = fmaf(__ldg(&w2row[l]), __ldg(&wde[l * 64]), acc);
        g_R[m * 32000 + j * 64 + e] = acc;
        return;
    }
    __shared__ int sw[16];
    int bid = b - 126;
    int i = bid * 512 + t;
    int v = (i < NN) ? g_degD[i] : 0;
#pragma unroll
    for (int o = 16; o >= 1; o >>= 1) v += __shfl_xor_sync(0xFFFFFFFFu, v, o);
    if ((t & 31) == 0) sw[t >> 5] = v;
    __syncthreads();
    if (t < 32) {
        int x = (t < 16) ? sw[t] : 0;
#pragma unroll
        for (int o = 8; o >= 1; o >>= 1) x += __shfl_xor_sync(0xFFFFFFFFu, x, o);
        if (t == 0) g_bsum[bid] = x;
    }
}

// ---- L3: MB (blocks 0..499, all 512 thr) + scanC (blocks 500..597) ------------
__global__ __launch_bounds__(512) void k_MBscan(const float* __restrict__ W1) {
    int b = blockIdx.x;
    int t = threadIdx.x;
    if (b < 500) {
        __shared__ float sA[8][500];
        __shared__ float red[7][8][64];
        int m = b / 250, i0 = (b % 250) * 8;
        for (int idx = t; idx < 4000; idx += 512) {
            int r = idx / 500, j = idx - r * 500;
            sA[r][j] = W1[m * 1000000 + (i0 + r) * 500 + j] * g_alpha1[m * 500 + j];
        }
        __syncthreads();
        int e = t & 63, jp = t >> 6;
        float acc[8] = {0, 0, 0, 0, 0, 0, 0, 0};
        for (int j = jp; j < 500; j += 8) {
            float w = g_R[m * 32000 + j * 64 + e];
#pragma unroll
            for (int r = 0; r < 8; r++) acc[r] += sA[r][j] * w;
        }
        if (jp > 0) {
#pragma unroll
            for (int r = 0; r < 8; r++) red[jp - 1][r][e] = acc[r];
        }
        __syncthreads();
        if (jp == 0) {
#pragma unroll
            for (int r = 0; r < 8; r++) {
                float v = acc[r];
#pragma unroll
                for (int p = 0; p < 7; p++) v += red[p][r][e];
                g_Bhi[e * 4096 + m * 2048 + i0 + r] = __float2half_rn(v * BSCALE);
            }
        }
        return;
    }
    __shared__ int sd[512];
    __shared__ int sboff;
    int bid = b - 500;
    int i = bid * 512 + t;
    int v = (i < NN) ? g_degD[i] : 0;
    sd[t] = v;
    __syncthreads();
    for (int s = 1; s < 512; s <<= 1) {
        int x = (t >= s) ? sd[t - s] : 0;
        __syncthreads();
        sd[t] += x;
        __syncthreads();
    }
    if (t == 0) {
        int run = 0;
        for (int j = 0; j < bid; j++) run += g_bsum[j];
        sboff = run;
        if (bid == 0) g_off[NN] = EE;
    }
    __syncthreads();
    if (i < NN) {
        g_off[i] = sboff + sd[t] - v;
        g_cs[i] = rsqrtf(fmaxf((float)g_degS[i], 1.0f));
        g_cd[i] = rsqrtf(fmaxf((float)v, 1.0f));
    }
}

// ---- L4: 64x64-tile single-term fp16 HMMA GEMM (splitK=4) + fill + rezero ------
#define SM_A 0                       // 2 buf x 8192 (fp16 A, 64 rows)
#define SM_B 16384                   // 2 buf x 8192 (fp16 B)
#define SMEM_BYTES 32768
#define GEMM_BLKS 3128
#define FILL_BLKS 3125

__global__ __launch_bounds__(128, 4) void k_gemm_hmma(const float* __restrict__ h,
                                                      const int* __restrict__ src,
                                                      const int* __restrict__ dst) {
    int b = blockIdx.x;
    int tid = threadIdx.x;
    if (b >= GEMM_BLKS) {
        if (b < GEMM_BLKS + FILL_BLKS) {
            int e0 = (b - GEMM_BLKS) * 512;
#pragma unroll
            for (int it = 0; it < 4; it++) {
                int e = e0 + it * 128 + tid;
                g_esrc[g_off[dst[e]] + g_epos[e]] = src[e];
            }
        } else {
            int i0 = (b - GEMM_BLKS - FILL_BLKS) * 512;
#pragma unroll
            for (int it = 0; it < 4; it++) {
                int i = i0 + it * 128 + tid;
                if (i < NN) { g_degS[i] = 0; g_degD[i] = 0; }
            }
        }
        return;
    }

    extern __shared__ __align__(1024) char smem[];
    uint32_t sbase = smem_u32(smem);
    int lane = tid & 31, wid = tid >> 5;
    int wm = wid >> 1, wn = wid & 1;
    int bx = b % 782, by = b / 782;
    int row0 = bx * 64;
    int m = by >> 1, kh = by & 1;
    const float* hb = h + (long long)m * NN * DINN;
    const __half* bhi = g_Bhi + m * 2048 + kh * 1024;
    int kbase = kh * 1024;

    uint32_t swz = (uint32_t)(lane & 7) << 4;
    uint32_t aoff = (uint32_t)(wm * 32 + (lane & 15)) * 128;
    uint32_t acolsel = (uint32_t)(lane >> 4) << 4;
    uint32_t boff = (uint32_t)(wn * 32 + lane) * 128;

    float c_[2][4][4];
#pragma unroll
    for (int mt = 0; mt < 2; mt++)
#pragma unroll
        for (int nt = 0; nt < 4; nt++)
#pragma unroll
            for (int q = 0; q < 4; q++) c_[mt][nt][q] = 0.f;

    float4 va[8];

    auto ldgA = [&](int c) {
        int k0 = kbase + c * 64;
        const float* base = hb + (long long)row0 * DINN + k0;
        if (row0 + 64 <= NN && k0 + 64 <= 2000) {
#pragma unroll
            for (int i = 0; i < 8; i++) {
                int idx = tid + 128 * i;
                int r = idx >> 4, cg = idx & 15;
                va[i] = *reinterpret_cast<const float4*>(base + (long long)r * DINN + cg * 4);
            }
        } else {
#pragma unroll
            for (int i = 0; i < 8; i++) {
                int idx = tid + 128 * i;
                int r = idx >> 4, cg = idx & 15;
                if (row0 + r < NN && k0 + cg * 4 + 3 < 2000)
                    va[i] = *reinterpret_cast<const float4*>(base + (long long)r * DINN + cg * 4);
                else
                    va[i] = make_float4(0.f, 0.f, 0.f, 0.f);
            }
        }
    };

    auto cpB = [&](int c, int buf) {
        int k0 = c * 64;
        uint32_t bH = sbase + SM_B + buf * 8192;
#pragma unroll
        for (int i = 0; i < 4; i++) {
            int idx = tid + 128 * i;
            int r = idx >> 3, cg = idx & 7;
            uint32_t off = (uint32_t)r * 128 +
                           (((uint32_t)cg * 16) ^ (((uint32_t)r & 7) << 4));
            CP_ASYNC16(bH + off, bhi + r * 4096 + k0 + cg * 8);
        }
        CP_COMMIT();
    };

    auto stsA = [&](int buf) {
        uint32_t aH = SM_A + buf * 8192;
#pragma unroll
        for (int i = 0; i < 8; i++) {
            int idx = tid + 128 * i;
            int r = idx >> 4, cg = idx & 15;
            float4 v = va[i];
            __half2 h01 = __float22half2_rn(make_float2(v.x, v.y));
            __half2 h23 = __float22half2_rn(make_float2(v.z, v.w));
            uint32_t off = (uint32_t)r * 128 +
                           (((uint32_t)cg * 8) ^ (((uint32_t)r & 7) << 4));
            *reinterpret_cast<uint2*>(smem + aH + off) =
                make_uint2(*reinterpret_cast<uint32_t*>(&h01),
                           *reinterpret_cast<uint32_t*>(&h23));
        }
    };

    auto compute = [&](int buf) {
        uint32_t aH = sbase + SM_A + buf * 8192;
        uint32_t bH = sbase + SM_B + buf * 8192;
#pragma unroll
        for (int ks = 0; ks < 4; ks++) {
            uint32_t kb = (uint32_t)ks * 32;
            uint32_t aF[2][4];
            uint32_t b0h[4], b1h[4];
#pragma unroll
            for (int mt = 0; mt < 2; mt++) {
                uint32_t adr = aoff + (uint32_t)mt * 2048 + ((kb + acolsel) ^ swz);
                LDSM4(aF[mt], aH + adr);
            }
            LDSM4(b0h, bH + boff + ((kb + 0) ^ swz));
            LDSM4(b1h, bH + boff + ((kb + 16) ^ swz));
#pragma unroll
            for (int mt = 0; mt < 2; mt++)
#pragma unroll
                for (int nt = 0; nt < 4; nt++)
                    MMA2(c_[mt][nt], aF[mt], b0h[nt], b1h[nt]);
        }
    };

    ldgA(0);
    cpB(0, 0);
    stsA(0);
    CP_WAIT0();
    __syncthreads();

    for (int c = 0; c < 16; c++) {
        int buf = c & 1;
        bool more = (c + 1 < 16);
        if (more) {
            ldgA(c + 1);
            cpB(c + 1, buf ^ 1);
        }
        compute(buf);
        if (more) {
            stsA(buf ^ 1);
            CP_WAIT0();
            __syncthreads();
        }
    }

    int g = lane >> 2;
    int base_r = row0 + wm * 32 + g;
    int col0 = wn * 32 + (lane & 3) * 2;
#pragma unroll
    for (int mt = 0; mt < 2; mt++) {
#pragma unroll
        for (int rr = 0; rr < 2; rr++) {
            int gr = base_r + mt * 16 + rr * 8;
            if (gr < NN) {
#pragma unroll
                for (int nt = 0; nt < 4; nt++) {
                    int col = col0 + nt * 8;
                    float2 v;
                    v.x = c_[mt][nt][rr * 2 + 0] * BINV;
                    v.y = c_[mt][nt][rr * 2 + 1] * BINV;
                    atomicAdd(reinterpret_cast<float2*>(&g_xw0[gr * 64 + col]), v);
                }
            }
        }
    }
}

// ---- L5: gather cs*(xw0+c') + relu/bias/norm + GEMV 64->32 -> xw1 -------------
__global__ __launch_bounds__(256) void k_g64(const float* __restrict__ bg0,
                                             const float* __restrict__ Wg1) {
    __shared__ float sW[64 * 32];
    __shared__ float sb[64];
    __shared__ float sc[64];
    int t = threadIdx.x;
    for (int i = t; i < 2048; i += 256) sW[i] = Wg1[i];
    if (t < 64) { sb[t] = bg0[t]; sc[t] = g_cprime[t]; }
    __syncthreads();
    int wid = t >> 5, lane = t & 31;
    int n = blockIdx.x * 8 + wid;
    if (n >= NN) return;
    int beg = g_off[n], end = g_off[n + 1];
    int half = lane >> 4, l16 = lane & 15;
    float4 acc = make_float4(0.f, 0.f, 0.f, 0.f);
    float scs = 0.f;
    int i = beg + half;
    while (i + 6 < end) {
        int s0 = __ldg(&g_esrc[i]), s1 = __ldg(&g_esrc[i + 2]);
        int s2 = __ldg(&g_esrc[i + 4]), s3 = __ldg(&g_esrc[i + 6]);
        float cs0 = __ldg(&g_cs[s0]), cs1 = __ldg(&g_cs[s1]);
        float cs2 = __ldg(&g_cs[s2]), cs3 = __ldg(&g_cs[s3]);
        float4 v0 = __ldg(reinterpret_cast<const float4*>(&g_xw0[s0 * 64 + l16 * 4]));
        float4 v1 = __ldg(reinterpret_cast<const float4*>(&g_xw0[s1 * 64 + l16 * 4]));
        float4 v2 = __ldg(reinterpret_cast<const float4*>(&g_xw0[s2 * 64 + l16 * 4]));
        float4 v3 = __ldg(reinterpret_cast<const float4*>(&g_xw0[s3 * 64 + l16 * 4]));
        acc.x += v0.x * cs0 + v1.x * cs1 + v2.x * cs2 + v3.x * cs3;
        acc.y += v0.y * cs0 + v1.y * cs1 + v2.y * cs2 + v3.y * cs3;
        acc.z += v0.z * cs0 + v1.z * cs1 + v2.z * cs2 + v3.z * cs3;
        acc.w += v0.w * cs0 + v1.w * cs1 + v2.w * cs2 + v3.w * cs3;
        scs += cs0 + cs1 + cs2 + cs3;
        i += 8;
    }
    while (i < end) {
        int s = __ldg(&g_esrc[i]);
        float cs0 = __ldg(&g_cs[s]);
        float4 v = __ldg(reinterpret_cast<const float4*>(&g_xw0[s * 64 + l16 * 4]));
        acc.x += v.x * cs0; acc.y += v.y * cs0; acc.z += v.z * cs0; acc.w += v.w * cs0;
        scs += cs0;
        i += 2;
    }
    acc.x += __shfl_xor_sync(0xFFFFFFFFu, acc.x, 16);
    acc.y += __shfl_xor_sync(0xFFFFFFFFu, acc.y, 16);
    acc.z += __shfl_xor_sync(0xFFFFFFFFu, acc.z, 16);
    acc.w += __shfl_xor_sync(0xFFFFFFFFu, acc.w, 16);
    scs   += __shfl_xor_sync(0xFFFFFFFFu, scs, 16);
    float cdv = g_cd[n], csv = g_cs[n];
    float val[4];
    val[0] = fmaxf(fmaf(fmaf(sc[l16 * 4 + 0], scs, acc.x), cdv, sb[l16 * 4 + 0]), 0.f) * csv;
    val[1] = fmaxf(fmaf(fmaf(sc[l16 * 4 + 1], scs, acc.y), cdv, sb[l16 * 4 + 1]), 0.f) * csv;
    val[2] = fmaxf(fmaf(fmaf(sc[l16 * 4 + 2], scs, acc.z), cdv, sb[l16 * 4 + 2]), 0.f) * csv;
    val[3] = fmaxf(fmaf(fmaf(sc[l16 * 4 + 3], scs, acc.w), cdv, sb[l16 * 4 + 3]), 0.f) * csv;
    float o = 0.f;
#pragma unroll
    for (int d = 0; d < 64; d++) {
        float v = __shfl_sync(0xFFFFFFFFu, val[d & 3], d >> 2);
        o = fmaf(v, sW[d * 32 + lane], o);
    }
    g_xw1[n * 32 + lane] = o;
}

// ---- L6: gather xw1 + relu/bias/norm + GEMV 32->4 -> xw2 ----------------------
__global__ __launch_bounds__(256) void k_g32(const float* __restrict__ bg1,
                                             const float* __restrict__ Wg2) {
    __shared__ float sW[32 * 4];
    __shared__ float sb[32];
    int t = threadIdx.x;
    if (t < 128) sW[t] = Wg2[t];
    if (t < 32) sb[t] = bg1[t];
    __syncthreads();
    int wid = t >> 5, lane = t & 31;
    int n = blockIdx.x * 8 + wid;
    if (n >= NN) return;
    int beg = g_off[n], end = g_off[n + 1];
    int q = lane >> 3, l8 = lane & 7;
    float4 acc = make_float4(0.f, 0.f, 0.f, 0.f);
    int i = beg + q;
    while (i + 12 < end) {
        int s0 = __ldg(&g_esrc[i]), s1 = __ldg(&g_esrc[i + 4]);
        int s2 = __ldg(&g_esrc[i + 8]), s3 = __ldg(&g_esrc[i + 12]);
        float4 v0 = __ldg(reinterpret_cast<const float4*>(&g_xw1[s0 * 32 + l8 * 4]));
        float4 v1 = __ldg(reinterpret_cast<const float4*>(&g_xw1[s1 * 32 + l8 * 4]));
        float4 v2 = __ldg(reinterpret_cast<const float4*>(&g_xw1[s2 * 32 + l8 * 4]));
        float4 v3 = __ldg(reinterpret_cast<const float4*>(&g_xw1[s3 * 32 + l8 * 4]));
        acc.x += v0.x + v1.x + v2.x + v3.x;
        acc.y += v0.y + v1.y + v2.y + v3.y;
        acc.z += v0.z + v1.z + v2.z + v3.z;
        acc.w += v0.w + v1.w + v2.w + v3.w;
        i += 16;
    }
    while (i < end) {
        int s = __ldg(&g_esrc[i]);
        float4 v = __ldg(reinterpret_cast<const float4*>(&g_xw1[s * 32 + l8 * 4]));
        acc.x += v.x; acc.y += v.y; acc.z += v.z; acc.w += v.w;
        i += 4;
    }
    acc.x += __shfl_xor_sync(0xFFFFFFFFu, acc.x, 8);
    acc.y += __shfl_xor_sync(0xFFFFFFFFu, acc.y, 8);
    acc.z += __shfl_xor_sync(0xFFFFFFFFu, acc.z, 8);
    acc.w += __shfl_xor_sync(0xFFFFFFFFu, acc.w, 8);
    acc.x += __shfl_xor_sync(0xFFFFFFFFu, acc.x, 16);
    acc.y += __shfl_xor_sync(0xFFFFFFFFu, acc.y, 16);
    acc.z += __shfl_xor_sync(0xFFFFFFFFu, acc.z, 16);
    acc.w += __shfl_xor_sync(0xFFFFFFFFu, acc.w, 16);
    float cdv = g_cd[n], csv = g_cs[n];
    float val[4];
    val[0] = fmaxf(fmaf(acc.x, cdv, sb[l8 * 4 + 0]), 0.f) * csv;
    val[1] = fmaxf(fmaf(acc.y, cdv, sb[l8 * 4 + 1]), 0.f) * csv;
    val[2] = fmaxf(fmaf(acc.z, cdv, sb[l8 * 4 + 2]), 0.f) * csv;
    val[3] = fmaxf(fmaf(acc.w, cdv, sb[l8 * 4 + 3]), 0.f) * csv;
    float o = 0.f;
#pragma unroll
    for (int d = 0; d < 32; d++) {
        float v = __shfl_sync(0xFFFFFFFFu, val[d & 3], d >> 2);
        o = fmaf(v, sW[d * 4 + (lane & 3)], o);
    }
    if (lane < 4) g_xw2[n * 4 + lane] = o;
}

// ---- L7: gather xw2 + bias -> out ---------------------------------------------
__global__ __launch_bounds__(256) void k_g4(const float* __restrict__ bg2,
                                            float* __restrict__ out) {
    int t = threadIdx.x;
    int wid = t >> 5, lane = t & 31;
    int n = blockIdx.x * 8 + wid;
    if (n >= NN) return;
    int beg = g_off[n], end = g_off[n + 1];
    float4 acc = make_float4(0.f, 0.f, 0.f, 0.f);
    for (int i = beg + lane; i < end; i += 32) {
        int s = __ldg(&g_esrc[i]);
        float4 v = __ldg(reinterpret_cast<const float4*>(&g_xw2[s * 4]));
        acc.x += v.x; acc.y += v.y; acc.z += v.z; acc.w += v.w;
    }
#pragma unroll
    for (int off = 16; off >= 1; off >>= 1) {
        acc.x += __shfl_xor_sync(0xFFFFFFFFu, acc.x, off);
        acc.y += __shfl_xor_sync(0xFFFFFFFFu, acc.y, off);
        acc.z += __shfl_xor_sync(0xFFFFFFFFu, acc.z, off);
        acc.w += __shfl_xor_sync(0xFFFFFFFFu, acc.w, off);
    }
    if (lane == 0) {
        float cdv = g_cd[n];
        float4 o;
        o.x = fmaf(acc.x, cdv, bg2[0]);
        o.y = fmaf(acc.y, cdv, bg2[1]);
        o.z = fmaf(acc.z, cdv, bg2[2]);
        o.w = fmaf(acc.w, cdv, bg2[3]);
        *reinterpret_cast<float4*>(&out[n * 4]) = o;
    }
}

// ---------------- launch ----------------
extern "C" void kernel_launch(void* const* d_in, const int* in_sizes, int n_in,
                              void* d_out, int out_size) {
    const float* h   = (const float*)d_in[0];
    const int*   src = (const int*)d_in[1];
    const int*   dst = (const int*)d_in[2];
    const float* W1  = (const float*)d_in[3];
    const float* b1  = (const float*)d_in[4];
    const float* g1  = (const float*)d_in[5];
    const float* be1 = (const float*)d_in[6];
    const float* m1  = (const float*)d_in[7];
    const float* v1  = (const float*)d_in[8];
    const float* W2  = (const float*)d_in[9];
    const float* b2  = (const float*)d_in[10];
    const float* g2  = (const float*)d_in[11];
    const float* be2 = (const float*)d_in[12];
    const float* m2  = (const float*)d_in[13];
    const float* v2  = (const float*)d_in[14];
    const float* Wd  = (const float*)d_in[15];
    const float* bd  = (const float*)d_in[16];
    const float* Wg0 = (const float*)d_in[17];
    const float* bg0 = (const float*)d_in[18];
    const float* Wg1 = (const float*)d_in[19];
    const float* bg1 = (const float*)d_in[20];
    const float* Wg2 = (const float*)d_in[21];
    const float* bg2 = (const float*)d_in[22];
    float* out = (float*)d_out;

    cudaFuncSetAttribute(k_gemm_hmma, cudaFuncAttributeMaxDynamicSharedMemorySize,
                         SMEM_BYTES);

    k_fold<<<3326, 512>>>(src, dst, b1, g1, be1, m1, v1, W2, b2, g2,   // 1
                          be2, m2, v2, Wd, bd, Wg0);
    k_Rscan<<<224, 512>>>(W2);                                         // 2
    k_MBscan<<<598, 512>>>(W1);                                        // 3
    k_gemm_hmma<<<GEMM_BLKS + FILL_BLKS + 98, 128, SMEM_BYTES>>>(h, src, dst);  // 4 <- ncu
    k_g64<<<(NN + 7) / 8, 256>>>(bg0, Wg1);                            // 5
    k_g32<<<(NN + 7) / 8, 256>>>(bg1, Wg2);                            // 6
    k_g4<<<(NN + 7) / 8, 256>>>(bg2, out);                             // 7
}

// round 13
// speedup vs baseline: 1.2234x; 1.1112x over previous
#include <cuda_runtime.h>
#include <cuda_fp16.h>
#include <cstdint>

#define NN   50000
#define EE   1600000
#define DINN 2000
#define BSCALE 4096.0f
#define BINV   (1.0f / 4096.0f)

// ---------------- device scratch (allocation-free contract) ----------------
__device__ float g_alpha1[2 * 500];
__device__ float g_t2b[2 * 128];
__device__ float g_cprime[64];
__device__ float g_Wde2[2 * 128 * 64];   // 0.5 * alpha2[l] * (Wd @ Wg0)
__device__ float g_R[2 * 500 * 64];      // W2 @ Wde2
__device__ __half g_Bhi[64 * 4096];      // [e][m*2048+k] fp16 of 4096*M^T (pad zero)
__device__ float g_xw0[NN * 64];         // fp32 splitK accumulation target
__device__ float g_xw1[NN * 32];
__device__ float g_xw2[NN * 4];
__device__ float g_cs[NN];
__device__ float g_cd[NN];
__device__ int   g_degS[NN];             // zero at load; re-zeroed each call
__device__ int   g_degD[NN];
__device__ int   g_off[NN + 1];
__device__ int   g_epos[EE];
__device__ int   g_esrc[EE];
__device__ int   g_bsum[128];

// ---------------- PTX helpers ----------------
__device__ __forceinline__ uint32_t smem_u32(const void* p) {
    uint32_t a;
    asm("{ .reg .u64 t; cvta.to.shared.u64 t, %1; cvt.u32.u64 %0, t; }"
        : "=r"(a) : "l"(p));
    return a;
}

#define LDSM4(r, a) \
    asm volatile("ldmatrix.sync.aligned.m8n8.x4.shared.b16 {%0,%1,%2,%3}, [%4];" \
                 : "=r"((r)[0]), "=r"((r)[1]), "=r"((r)[2]), "=r"((r)[3]) : "r"(a))

#define MMA2(c, a, b0, b1) \
    asm volatile( \
        "mma.sync.aligned.m16n8k16.row.col.f32.f16.f16.f32 " \
        "{%0,%1,%2,%3}, {%4,%5,%6,%7}, {%8,%9}, {%0,%1,%2,%3};" \
        : "+f"((c)[0]), "+f"((c)[1]), "+f"((c)[2]), "+f"((c)[3]) \
        : "r"((a)[0]), "r"((a)[1]), "r"((a)[2]), "r"((a)[3]), \
          "r"(b0), "r"(b1))

#define CP_ASYNC16(dst, src) \
    asm volatile("cp.async.cg.shared.global [%0], [%1], 16;" \
                 :: "r"(dst), "l"(src) : "memory")
#define CP_COMMIT() asm volatile("cp.async.commit_group;" ::: "memory")
#define CP_WAIT0()  asm volatile("cp.async.wait_group 0;" ::: "memory")

// ---- L1: Wde2 (blk 0..31) + t2b (blk 32) + edges (33..3157) + zero (3158..) ---
__global__ __launch_bounds__(512) void k_fold(
    const int* __restrict__ src, const int* __restrict__ dst,
    const float* __restrict__ b1, const float* __restrict__ g1,
    const float* __restrict__ be1, const float* __restrict__ m1,
    const float* __restrict__ v1, const float* __restrict__ W2,
    const float* __restrict__ b2, const float* __restrict__ g2,
    const float* __restrict__ be2, const float* __restrict__ m2,
    const float* __restrict__ v2, const float* __restrict__ Wd,
    const float* __restrict__ bd, const float* __restrict__ Wg0) {
    int b = blockIdx.x;
    int t = threadIdx.x;
    if (b < 32) {
        // Wde2[m][l][e] = 0.5*alpha2[m][l]*sum_d Wd[m][l][d]*Wg0[d][e]
        int idx = b * 512 + t;
        int m = idx >> 13, l = (idx >> 6) & 127, e = idx & 63;
        float a2 = g2[m * 128 + l] * rsqrtf(v2[m * 128 + l] + 1e-5f);
        const float* wdrow = Wd + m * 8192 + l * 64;
        float s = 0.f;
#pragma unroll 4
        for (int d = 0; d < 64; d++)
            s = fmaf(__ldg(&wdrow[d]), __ldg(&Wg0[d * 64 + e]), s);
        g_Wde2[idx] = 0.5f * a2 * s;
        return;
    }
    if (b == 32) {
        __shared__ float sbb1[1000];
        for (int i = t; i < 1000; i += 512) {
            float a = g1[i] * rsqrtf(v1[i] + 1e-5f);
            g_alpha1[i] = a;
            sbb1[i] = (b1[i] - m1[i]) * a + be1[i];
        }
        __syncthreads();
        if (t < 256) {
            int mm = t >> 7, l = t & 127;
            float s = 0.f;
            for (int j = 0; j < 500; j++)
                s += sbb1[mm * 500 + j] * W2[mm * 64000 + j * 128 + l];
            float a2 = g2[t] * rsqrtf(v2[t] + 1e-5f);
            g_t2b[t] = (s + b2[t] - m2[t]) * a2 + be2[t];
        }
        return;
    }
    if (b < 33 + 3125) {
        int e = (b - 33) * 512 + t;
        if (e < EE) {
            g_epos[e] = atomicAdd(&g_degD[dst[e]], 1);
            atomicAdd(&g_degS[src[e]], 1);
        }
        return;
    }
    float4 z = make_float4(0.f, 0.f, 0.f, 0.f);
    for (int i = (b - 3158) * 512 + t; i < NN * 16; i += 200 * 512)
        reinterpret_cast<float4*>(g_xw0)[i] = z;
}

// ---- L2: R (blk 0..125) + scanA (126..223) + cprime (224) ---------------------
__global__ __launch_bounds__(512) void k_Rscan(const float* __restrict__ W2,
                                               const float* __restrict__ Wd,
                                               const float* __restrict__ bd,
                                               const float* __restrict__ Wg0) {
    int b = blockIdx.x;
    int t = threadIdx.x;
    if (b < 126) {
        int m = b / 63, j0 = (b % 63) * 8;
        int jr = t >> 6, e = t & 63;
        int j = j0 + jr;
        if (j >= 500) return;
        const float* w2row = W2 + m * 64000 + j * 128;
        const float* wde = g_Wde2 + m * 8192 + e;
        float acc = 0.f;
#pragma unroll 4
        for (int l = 0; l < 128; l++)
            acc = fmaf(__ldg(&w2row[l]), __ldg(&wde[l * 64]), acc);
        g_R[m * 32000 + j * 64 + e] = acc;
        return;
    }
    if (b < 224) {
        __shared__ int sw[16];
        int bid = b - 126;
        int i = bid * 512 + t;
        int v = (i < NN) ? g_degD[i] : 0;
#pragma unroll
        for (int o = 16; o >= 1; o >>= 1) v += __shfl_xor_sync(0xFFFFFFFFu, v, o);
        if ((t & 31) == 0) sw[t >> 5] = v;
        __syncthreads();
        if (t < 32) {
            int x = (t < 16) ? sw[t] : 0;
#pragma unroll
            for (int o = 8; o >= 1; o >>= 1) x += __shfl_xor_sync(0xFFFFFFFFu, x, o);
            if (t == 0) g_bsum[bid] = x;
        }
        return;
    }
    // cprime: cmean[d] = 0.5*(sum_m bd + t2b@Wd), cprime[e] = cmean @ Wg0
    __shared__ float scm[64];
    if (t < 64) {
        int d = t;
        float s = 0.f;
        for (int mm = 0; mm < 2; mm++) {
            float sm = bd[mm * 64 + d];
            for (int l = 0; l < 128; l++)
                sm += g_t2b[mm * 128 + l] * Wd[mm * 8192 + l * 64 + d];
            s += sm;
        }
        scm[d] = 0.5f * s;
    }
    __syncthreads();
    if (t < 64) {
        float s = 0.f;
        for (int d = 0; d < 64; d++) s += scm[d] * Wg0[d * 64 + t];
        g_cprime[t] = s;
    }
}

// ---- L3: MB (blocks 0..499) + scanC (blocks 500..597) -------------------------
__global__ __launch_bounds__(512) void k_MBscan(const float* __restrict__ W1) {
    int b = blockIdx.x;
    int t = threadIdx.x;
    if (b < 500) {
        __shared__ float sA[8][500];
        __shared__ float red[7][8][64];
        int m = b / 250, i0 = (b % 250) * 8;
        for (int idx = t; idx < 4000; idx += 512) {
            int r = idx / 500, j = idx - r * 500;
            sA[r][j] = W1[m * 1000000 + (i0 + r) * 500 + j] * g_alpha1[m * 500 + j];
        }
        __syncthreads();
        int e = t & 63, jp = t >> 6;
        float acc[8] = {0, 0, 0, 0, 0, 0, 0, 0};
        for (int j = jp; j < 500; j += 8) {
            float w = g_R[m * 32000 + j * 64 + e];
#pragma unroll
            for (int r = 0; r < 8; r++) acc[r] += sA[r][j] * w;
        }
        if (jp > 0) {
#pragma unroll
            for (int r = 0; r < 8; r++) red[jp - 1][r][e] = acc[r];
        }
        __syncthreads();
        if (jp == 0) {
#pragma unroll
            for (int r = 0; r < 8; r++) {
                float v = acc[r];
#pragma unroll
                for (int p = 0; p < 7; p++) v += red[p][r][e];
                g_Bhi[e * 4096 + m * 2048 + i0 + r] = __float2half_rn(v * BSCALE);
            }
        }
        return;
    }
    __shared__ int sd[512];
    __shared__ int sboff;
    int bid = b - 500;
    int i = bid * 512 + t;
    int v = (i < NN) ? g_degD[i] : 0;
    sd[t] = v;
    __syncthreads();
    for (int s = 1; s < 512; s <<= 1) {
        int x = (t >= s) ? sd[t - s] : 0;
        __syncthreads();
        sd[t] += x;
        __syncthreads();
    }
    if (t == 0) {
        int run = 0;
        for (int j = 0; j < bid; j++) run += g_bsum[j];
        sboff = run;
        if (bid == 0) g_off[NN] = EE;
    }
    __syncthreads();
    if (i < NN) {
        g_off[i] = sboff + sd[t] - v;
        g_cs[i] = rsqrtf(fmaxf((float)g_degS[i], 1.0f));
        g_cd[i] = rsqrtf(fmaxf((float)v, 1.0f));
    }
}

// ---- L4: 64x64-tile single-term fp16 HMMA GEMM (splitK=4) + fill + rezero ------
#define SM_A 0                       // 2 buf x 8192 (fp16 A, 64 rows)
#define SM_B 16384                   // 2 buf x 8192 (fp16 B)
#define SMEM_BYTES 32768
#define GEMM_BLKS 3128
#define FILL_BLKS 3125

__global__ __launch_bounds__(128, 5) void k_gemm_hmma(const float* __restrict__ h,
                                                      const int* __restrict__ src,
                                                      const int* __restrict__ dst) {
    int b = blockIdx.x;
    int tid = threadIdx.x;
    if (b >= GEMM_BLKS) {
        if (b < GEMM_BLKS + FILL_BLKS) {
            int e0 = (b - GEMM_BLKS) * 512;
#pragma unroll
            for (int it = 0; it < 4; it++) {
                int e = e0 + it * 128 + tid;
                g_esrc[g_off[dst[e]] + g_epos[e]] = src[e];
            }
        } else {
            int i0 = (b - GEMM_BLKS - FILL_BLKS) * 512;
#pragma unroll
            for (int it = 0; it < 4; it++) {
                int i = i0 + it * 128 + tid;
                if (i < NN) { g_degS[i] = 0; g_degD[i] = 0; }
            }
        }
        return;
    }

    extern __shared__ __align__(1024) char smem[];
    uint32_t sbase = smem_u32(smem);
    int lane = tid & 31, wid = tid >> 5;
    int wm = wid >> 1, wn = wid & 1;
    int bx = b % 782, by = b / 782;
    int row0 = bx * 64;
    int m = by >> 1, kh = by & 1;
    const float* hb = h + (long long)m * NN * DINN;
    const __half* bhi = g_Bhi + m * 2048 + kh * 1024;
    int kbase = kh * 1024;

    uint32_t swz = (uint32_t)(lane & 7) << 4;
    uint32_t aoff = (uint32_t)(wm * 32 + (lane & 15)) * 128;
    uint32_t acolsel = (uint32_t)(lane >> 4) << 4;
    uint32_t boff = (uint32_t)(wn * 32 + lane) * 128;

    float c_[2][4][4];
#pragma unroll
    for (int mt = 0; mt < 2; mt++)
#pragma unroll
        for (int nt = 0; nt < 4; nt++)
#pragma unroll
            for (int q = 0; q < 4; q++) c_[mt][nt][q] = 0.f;

    float4 va[8];

    auto ldgA = [&](int c) {
        int k0 = kbase + c * 64;
        const float* base = hb + (long long)row0 * DINN + k0;
        if (row0 + 64 <= NN && k0 + 64 <= 2000) {
#pragma unroll
            for (int i = 0; i < 8; i++) {
                int idx = tid + 128 * i;
                int r = idx >> 4, cg = idx & 15;
                va[i] = *reinterpret_cast<const float4*>(base + (long long)r * DINN + cg * 4);
            }
        } else {
#pragma unroll
            for (int i = 0; i < 8; i++) {
                int idx = tid + 128 * i;
                int r = idx >> 4, cg = idx & 15;
                if (row0 + r < NN && k0 + cg * 4 + 3 < 2000)
                    va[i] = *reinterpret_cast<const float4*>(base + (long long)r * DINN + cg * 4);
                else
                    va[i] = make_float4(0.f, 0.f, 0.f, 0.f);
            }
        }
    };

    auto cpB = [&](int c, int buf) {
        int k0 = c * 64;
        uint32_t bH = sbase + SM_B + buf * 8192;
#pragma unroll
        for (int i = 0; i < 4; i++) {
            int idx = tid + 128 * i;
            int r = idx >> 3, cg = idx & 7;
            uint32_t off = (uint32_t)r * 128 +
                           (((uint32_t)cg * 16) ^ (((uint32_t)r & 7) << 4));
            CP_ASYNC16(bH + off, bhi + r * 4096 + k0 + cg * 8);
        }
        CP_COMMIT();
    };

    auto stsA = [&](int buf) {
        uint32_t aH = SM_A + buf * 8192;
#pragma unroll
        for (int i = 0; i < 8; i++) {
            int idx = tid + 128 * i;
            int r = idx >> 4, cg = idx & 15;
            float4 v = va[i];
            __half2 h01 = __float22half2_rn(make_float2(v.x, v.y));
            __half2 h23 = __float22half2_rn(make_float2(v.z, v.w));
            uint32_t off = (uint32_t)r * 128 +
                           (((uint32_t)cg * 8) ^ (((uint32_t)r & 7) << 4));
            *reinterpret_cast<uint2*>(smem + aH + off) =
                make_uint2(*reinterpret_cast<uint32_t*>(&h01),
                           *reinterpret_cast<uint32_t*>(&h23));
        }
    };

    auto compute = [&](int buf) {
        uint32_t aH = sbase + SM_A + buf * 8192;
        uint32_t bH = sbase + SM_B + buf * 8192;
#pragma unroll
        for (int ks = 0; ks < 4; ks++) {
            uint32_t kb = (uint32_t)ks * 32;
            uint32_t aF[2][4];
            uint32_t b0h[4], b1h[4];
#pragma unroll
            for (int mt = 0; mt < 2; mt++) {
                uint32_t adr = aoff + (uint32_t)mt * 2048 + ((kb + acolsel) ^ swz);
                LDSM4(aF[mt], aH + adr);
            }
            LDSM4(b0h, bH + boff + ((kb + 0) ^ swz));
            LDSM4(b1h, bH + boff + ((kb + 16) ^ swz));
#pragma unroll
            for (int mt = 0; mt < 2; mt++)
#pragma unroll
                for (int nt = 0; nt < 4; nt++)
                    MMA2(c_[mt][nt], aF[mt], b0h[nt], b1h[nt]);
        }
    };

    ldgA(0);
    cpB(0, 0);
    stsA(0);
    CP_WAIT0();
    __syncthreads();

    for (int c = 0; c < 16; c++) {
        int buf = c & 1;
        bool more = (c + 1 < 16);
        if (more) {
            ldgA(c + 1);
            cpB(c + 1, buf ^ 1);
        }
        compute(buf);
        if (more) {
            stsA(buf ^ 1);
            CP_WAIT0();
            __syncthreads();
        }
    }

    int g = lane >> 2;
    int base_r = row0 + wm * 32 + g;
    int col0 = wn * 32 + (lane & 3) * 2;
#pragma unroll
    for (int mt = 0; mt < 2; mt++) {
#pragma unroll
        for (int rr = 0; rr < 2; rr++) {
            int gr = base_r + mt * 16 + rr * 8;
            if (gr < NN) {
#pragma unroll
                for (int nt = 0; nt < 4; nt++) {
                    int col = col0 + nt * 8;
                    float2 v;
                    v.x = c_[mt][nt][rr * 2 + 0] * BINV;
                    v.y = c_[mt][nt][rr * 2 + 1] * BINV;
                    atomicAdd(reinterpret_cast<float2*>(&g_xw0[gr * 64 + col]), v);
                }
            }
        }
    }
}

// ---- L5: gather cs*(xw0+c') + relu/bias/norm + GEMV 64->32 -> xw1 -------------
__global__ __launch_bounds__(256) void k_g64(const float* __restrict__ bg0,
                                             const float* __restrict__ Wg1) {
    __shared__ float sW[64 * 32];
    __shared__ float sb[64];
    __shared__ float sc[64];
    int t = threadIdx.x;
    for (int i = t; i < 2048; i += 256) sW[i] = Wg1[i];
    if (t < 64) { sb[t] = bg0[t]; sc[t] = g_cprime[t]; }
    __syncthreads();
    int wid = t >> 5, lane = t & 31;
    int n = blockIdx.x * 8 + wid;
    if (n >= NN) return;
    int beg = g_off[n], end = g_off[n + 1];
    int half = lane >> 4, l16 = lane & 15;
    float4 acc = make_float4(0.f, 0.f, 0.f, 0.f);
    float scs = 0.f;
    int i = beg + half;
    while (i + 6 < end) {
        int s0 = __ldg(&g_esrc[i]), s1 = __ldg(&g_esrc[i + 2]);
        int s2 = __ldg(&g_esrc[i + 4]), s3 = __ldg(&g_esrc[i + 6]);
        float cs0 = __ldg(&g_cs[s0]), cs1 = __ldg(&g_cs[s1]);
        float cs2 = __ldg(&g_cs[s2]), cs3 = __ldg(&g_cs[s3]);
        float4 v0 = __ldg(reinterpret_cast<const float4*>(&g_xw0[s0 * 64 + l16 * 4]));
        float4 v1 = __ldg(reinterpret_cast<const float4*>(&g_xw0[s1 * 64 + l16 * 4]));
        float4 v2 = __ldg(reinterpret_cast<const float4*>(&g_xw0[s2 * 64 + l16 * 4]));
        float4 v3 = __ldg(reinterpret_cast<const float4*>(&g_xw0[s3 * 64 + l16 * 4]));
        acc.x += v0.x * cs0 + v1.x * cs1 + v2.x * cs2 + v3.x * cs3;
        acc.y += v0.y * cs0 + v1.y * cs1 + v2.y * cs2 + v3.y * cs3;
        acc.z += v0.z * cs0 + v1.z * cs1 + v2.z * cs2 + v3.z * cs3;
        acc.w += v0.w * cs0 + v1.w * cs1 + v2.w * cs2 + v3.w * cs3;
        scs += cs0 + cs1 + cs2 + cs3;
        i += 8;
    }
    while (i < end) {
        int s = __ldg(&g_esrc[i]);
        float cs0 = __ldg(&g_cs[s]);
        float4 v = __ldg(reinterpret_cast<const float4*>(&g_xw0[s * 64 + l16 * 4]));
        acc.x += v.x * cs0; acc.y += v.y * cs0; acc.z += v.z * cs0; acc.w += v.w * cs0;
        scs += cs0;
        i += 2;
    }
    acc.x += __shfl_xor_sync(0xFFFFFFFFu, acc.x, 16);
    acc.y += __shfl_xor_sync(0xFFFFFFFFu, acc.y, 16);
    acc.z += __shfl_xor_sync(0xFFFFFFFFu, acc.z, 16);
    acc.w += __shfl_xor_sync(0xFFFFFFFFu, acc.w, 16);
    scs   += __shfl_xor_sync(0xFFFFFFFFu, scs, 16);
    float cdv = g_cd[n], csv = g_cs[n];
    float val[4];
    val[0] = fmaxf(fmaf(fmaf(sc[l16 * 4 + 0], scs, acc.x), cdv, sb[l16 * 4 + 0]), 0.f) * csv;
    val[1] = fmaxf(fmaf(fmaf(sc[l16 * 4 + 1], scs, acc.y), cdv, sb[l16 * 4 + 1]), 0.f) * csv;
    val[2] = fmaxf(fmaf(fmaf(sc[l16 * 4 + 2], scs, acc.z), cdv, sb[l16 * 4 + 2]), 0.f) * csv;
    val[3] = fmaxf(fmaf(fmaf(sc[l16 * 4 + 3], scs, acc.w), cdv, sb[l16 * 4 + 3]), 0.f) * csv;
    float o = 0.f;
#pragma unroll
    for (int d = 0; d < 64; d++) {
        float v = __shfl_sync(0xFFFFFFFFu, val[d & 3], d >> 2);
        o = fmaf(v, sW[d * 32 + lane], o);
    }
    g_xw1[n * 32 + lane] = o;
}

// ---- L6: gather xw1 + relu/bias/norm + GEMV 32->4 -> xw2 ----------------------
__global__ __launch_bounds__(256) void k_g32(const float* __restrict__ bg1,
                                             const float* __restrict__ Wg2) {
    __shared__ float sW[32 * 4];
    __shared__ float sb[32];
    int t = threadIdx.x;
    if (t < 128) sW[t] = Wg2[t];
    if (t < 32) sb[t] = bg1[t];
    __syncthreads();
    int wid = t >> 5, lane = t & 31;
    int n = blockIdx.x * 8 + wid;
    if (n >= NN) return;
    int beg = g_off[n], end = g_off[n + 1];
    int q = lane >> 3, l8 = lane & 7;
    float4 acc = make_float4(0.f, 0.f, 0.f, 0.f);
    int i = beg + q;
    while (i + 12 < end) {
        int s0 = __ldg(&g_esrc[i]), s1 = __ldg(&g_esrc[i + 4]);
        int s2 = __ldg(&g_esrc[i + 8]), s3 = __ldg(&g_esrc[i + 12]);
        float4 v0 = __ldg(reinterpret_cast<const float4*>(&g_xw1[s0 * 32 + l8 * 4]));
        float4 v1 = __ldg(reinterpret_cast<const float4*>(&g_xw1[s1 * 32 + l8 * 4]));
        float4 v2 = __ldg(reinterpret_cast<const float4*>(&g_xw1[s2 * 32 + l8 * 4]));
        float4 v3 = __ldg(reinterpret_cast<const float4*>(&g_xw1[s3 * 32 + l8 * 4]));
        acc.x += v0.x + v1.x + v2.x + v3.x;
        acc.y += v0.y + v1.y + v2.y + v3.y;
        acc.z += v0.z + v1.z + v2.z + v3.z;
        acc.w += v0.w + v1.w + v2.w + v3.w;
        i += 16;
    }
    while (i < end) {
        int s = __ldg(&g_esrc[i]);
        float4 v = __ldg(reinterpret_cast<const float4*>(&g_xw1[s * 32 + l8 * 4]));
        acc.x += v.x; acc.y += v.y; acc.z += v.z; acc.w += v.w;
        i += 4;
    }
    acc.x += __shfl_xor_sync(0xFFFFFFFFu, acc.x, 8);
    acc.y += __shfl_xor_sync(0xFFFFFFFFu, acc.y, 8);
    acc.z += __shfl_xor_sync(0xFFFFFFFFu, acc.z, 8);
    acc.w += __shfl_xor_sync(0xFFFFFFFFu, acc.w, 8);
    acc.x += __shfl_xor_sync(0xFFFFFFFFu, acc.x, 16);
    acc.y += __shfl_xor_sync(0xFFFFFFFFu, acc.y, 16);
    acc.z += __shfl_xor_sync(0xFFFFFFFFu, acc.z, 16);
    acc.w += __shfl_xor_sync(0xFFFFFFFFu, acc.w, 16);
    float cdv = g_cd[n], csv = g_cs[n];
    float val[4];
    val[0] = fmaxf(fmaf(acc.x, cdv, sb[l8 * 4 + 0]), 0.f) * csv;
    val[1] = fmaxf(fmaf(acc.y, cdv, sb[l8 * 4 + 1]), 0.f) * csv;
    val[2] = fmaxf(fmaf(acc.z, cdv, sb[l8 * 4 + 2]), 0.f) * csv;
    val[3] = fmaxf(fmaf(acc.w, cdv, sb[l8 * 4 + 3]), 0.f) * csv;
    float o = 0.f;
#pragma unroll
    for (int d = 0; d < 32; d++) {
        float v = __shfl_sync(0xFFFFFFFFu, val[d & 3], d >> 2);
        o = fmaf(v, sW[d * 4 + (lane & 3)], o);
    }
    if (lane < 4) g_xw2[n * 4 + lane] = o;
}

// ---- L7: gather xw2 + bias -> out ---------------------------------------------
__global__ __launch_bounds__(256) void k_g4(const float* __restrict__ bg2,
                                            float* __restrict__ out) {
    int t = threadIdx.x;
    int wid = t >> 5, lane = t & 31;
    int n = blockIdx.x * 8 + wid;
    if (n >= NN) return;
    int beg = g_off[n], end = g_off[n + 1];
    float4 acc = make_float4(0.f, 0.f, 0.f, 0.f);
    for (int i = beg + lane; i < end; i += 32) {
        int s = __ldg(&g_esrc[i]);
        float4 v = __ldg(reinterpret_cast<const float4*>(&g_xw2[s * 4]));
        acc.x += v.x; acc.y += v.y; acc.z += v.z; acc.w += v.w;
    }
#pragma unroll
    for (int off = 16; off >= 1; off >>= 1) {
        acc.x += __shfl_xor_sync(0xFFFFFFFFu, acc.x, off);
        acc.y += __shfl_xor_sync(0xFFFFFFFFu, acc.y, off);
        acc.z += __shfl_xor_sync(0xFFFFFFFFu, acc.z, off);
        acc.w += __shfl_xor_sync(0xFFFFFFFFu, acc.w, off);
    }
    if (lane == 0) {
        float cdv = g_cd[n];
        float4 o;
        o.x = fmaf(acc.x, cdv, bg2[0]);
        o.y = fmaf(acc.y, cdv, bg2[1]);
        o.z = fmaf(acc.z, cdv, bg2[2]);
        o.w = fmaf(acc.w, cdv, bg2[3]);
        *reinterpret_cast<float4*>(&out[n * 4]) = o;
    }
}

// ---------------- launch ----------------
extern "C" void kernel_launch(void* const* d_in, const int* in_sizes, int n_in,
                              void* d_out, int out_size) {
    const float* h   = (const float*)d_in[0];
    const int*   src = (const int*)d_in[1];
    const int*   dst = (const int*)d_in[2];
    const float* W1  = (const float*)d_in[3];
    const float* b1  = (const float*)d_in[4];
    const float* g1  = (const float*)d_in[5];
    const float* be1 = (const float*)d_in[6];
    const float* m1  = (const float*)d_in[7];
    const float* v1  = (const float*)d_in[8];
    const float* W2  = (const float*)d_in[9];
    const float* b2  = (const float*)d_in[10];
    const float* g2  = (const float*)d_in[11];
    const float* be2 = (const float*)d_in[12];
    const float* m2  = (const float*)d_in[13];
    const float* v2  = (const float*)d_in[14];
    const float* Wd  = (const float*)d_in[15];
    const float* bd  = (const float*)d_in[16];
    const float* Wg0 = (const float*)d_in[17];
    const float* bg0 = (const float*)d_in[18];
    const float* Wg1 = (const float*)d_in[19];
    const float* bg1 = (const float*)d_in[20];
    const float* Wg2 = (const float*)d_in[21];
    const float* bg2 = (const float*)d_in[22];
    float* out = (float*)d_out;

    cudaFuncSetAttribute(k_gemm_hmma, cudaFuncAttributeMaxDynamicSharedMemorySize,
                         SMEM_BYTES);

    k_fold<<<3358, 512>>>(src, dst, b1, g1, be1, m1, v1, W2, b2, g2,   // 1
                          be2, m2, v2, Wd, bd, Wg0);
    k_Rscan<<<225, 512>>>(W2, Wd, bd, Wg0);                            // 2
    k_MBscan<<<598, 512>>>(W1);                                        // 3
    k_gemm_hmma<<<GEMM_BLKS + FILL_BLKS + 98, 128, SMEM_BYTES>>>(h, src, dst);  // 4 <- ncu
    k_g64<<<(NN + 7) / 8, 256>>>(bg0, Wg1);                            // 5
    k_g32<<<(NN + 7) / 8, 256>>>(bg1, Wg2);                            // 6
    k_g4<<<(NN + 7) / 8, 256>>>(bg2, out);                             // 7
}

// round 14
// speedup vs baseline: 1.2678x; 1.0363x over previous
#include <cuda_runtime.h>
#include <cuda_fp16.h>
#include <cstdint>

#define NN   50000
#define EE   1600000
#define DINN 2000
#define BSCALE 4096.0f
#define BINV   (1.0f / 4096.0f)

// ---------------- device scratch (allocation-free contract) ----------------
__device__ float g_alpha1[2 * 500];
__device__ float g_t2b[2 * 128];
__device__ float g_cprime[64];
__device__ float g_Wde2[2 * 128 * 64];   // 0.5 * alpha2[l] * (Wd @ Wg0)
__device__ float g_R[2 * 500 * 64];      // W2 @ Wde2
__device__ __half g_Bhi[64 * 4096];      // [e][m*2048+k] fp16 of 4096*M^T (pad zero)
__device__ float g_xw0[NN * 64];         // fp32 splitK accumulation target
__device__ float g_xw1[NN * 32];
__device__ float g_xw2[NN * 4];
__device__ float g_cs[NN];
__device__ float g_cd[NN];
__device__ int   g_degS[NN];             // zero at load; re-zeroed each call
__device__ int   g_degD[NN];
__device__ int   g_off[NN + 1];
__device__ int   g_epos[EE];
__device__ int   g_esrc[EE];
__device__ int   g_bsum[128];

// ---------------- PTX helpers ----------------
__device__ __forceinline__ uint32_t smem_u32(const void* p) {
    uint32_t a;
    asm("{ .reg .u64 t; cvta.to.shared.u64 t, %1; cvt.u32.u64 %0, t; }"
        : "=r"(a) : "l"(p));
    return a;
}

#define LDSM4(r, a) \
    asm volatile("ldmatrix.sync.aligned.m8n8.x4.shared.b16 {%0,%1,%2,%3}, [%4];" \
                 : "=r"((r)[0]), "=r"((r)[1]), "=r"((r)[2]), "=r"((r)[3]) : "r"(a))

#define MMA2(c, a, b0, b1) \
    asm volatile( \
        "mma.sync.aligned.m16n8k16.row.col.f32.f16.f16.f32 " \
        "{%0,%1,%2,%3}, {%4,%5,%6,%7}, {%8,%9}, {%0,%1,%2,%3};" \
        : "+f"((c)[0]), "+f"((c)[1]), "+f"((c)[2]), "+f"((c)[3]) \
        : "r"((a)[0]), "r"((a)[1]), "r"((a)[2]), "r"((a)[3]), \
          "r"(b0), "r"(b1))

#define CP_ASYNC16(dst, src) \
    asm volatile("cp.async.cg.shared.global [%0], [%1], 16;" \
                 :: "r"(dst), "l"(src) : "memory")
#define CP_COMMIT() asm volatile("cp.async.commit_group;" ::: "memory")
#define CP_WAIT0()  asm volatile("cp.async.wait_group 0;" ::: "memory")

// ---- L1: Wde2 (blk 0..31) + t2b (blk 32) + edges (33..3157) + zero (3158..) ---
__global__ __launch_bounds__(512) void k_fold(
    const int* __restrict__ src, const int* __restrict__ dst,
    const float* __restrict__ b1, const float* __restrict__ g1,
    const float* __restrict__ be1, const float* __restrict__ m1,
    const float* __restrict__ v1, const float* __restrict__ W2,
    const float* __restrict__ b2, const float* __restrict__ g2,
    const float* __restrict__ be2, const float* __restrict__ m2,
    const float* __restrict__ v2, const float* __restrict__ Wd,
    const float* __restrict__ bd, const float* __restrict__ Wg0) {
    int b = blockIdx.x;
    int t = threadIdx.x;
    if (b < 32) {
        int idx = b * 512 + t;
        int m = idx >> 13, l = (idx >> 6) & 127, e = idx & 63;
        float a2 = g2[m * 128 + l] * rsqrtf(v2[m * 128 + l] + 1e-5f);
        const float* wdrow = Wd + m * 8192 + l * 64;
        float s = 0.f;
#pragma unroll 4
        for (int d = 0; d < 64; d++)
            s = fmaf(__ldg(&wdrow[d]), __ldg(&Wg0[d * 64 + e]), s);
        g_Wde2[idx] = 0.5f * a2 * s;
        return;
    }
    if (b == 32) {
        __shared__ float sbb1[1000];
        for (int i = t; i < 1000; i += 512) {
            float a = g1[i] * rsqrtf(v1[i] + 1e-5f);
            g_alpha1[i] = a;
            sbb1[i] = (b1[i] - m1[i]) * a + be1[i];
        }
        __syncthreads();
        if (t < 256) {
            int mm = t >> 7, l = t & 127;
            float s = 0.f;
            for (int j = 0; j < 500; j++)
                s += sbb1[mm * 500 + j] * W2[mm * 64000 + j * 128 + l];
            float a2 = g2[t] * rsqrtf(v2[t] + 1e-5f);
            g_t2b[t] = (s + b2[t] - m2[t]) * a2 + be2[t];
        }
        return;
    }
    if (b < 33 + 3125) {
        int e = (b - 33) * 512 + t;
        if (e < EE) {
            g_epos[e] = atomicAdd(&g_degD[dst[e]], 1);
            atomicAdd(&g_degS[src[e]], 1);
        }
        return;
    }
    float4 z = make_float4(0.f, 0.f, 0.f, 0.f);
    for (int i = (b - 3158) * 512 + t; i < NN * 16; i += 200 * 512)
        reinterpret_cast<float4*>(g_xw0)[i] = z;
}

// ---- L2: R (blk 0..125) + scanA (126..223) + cprime (224) ---------------------
__global__ __launch_bounds__(512) void k_Rscan(const float* __restrict__ W2,
                                               const float* __restrict__ Wd,
                                               const float* __restrict__ bd,
                                               const float* __restrict__ Wg0) {
    int b = blockIdx.x;
    int t = threadIdx.x;
    if (b < 126) {
        int m = b / 63, j0 = (b % 63) * 8;
        int jr = t >> 6, e = t & 63;
        int j = j0 + jr;
        if (j >= 500) return;
        const float* w2row = W2 + m * 64000 + j * 128;
        const float* wde = g_Wde2 + m * 8192 + e;
        float acc = 0.f;
#pragma unroll 4
        for (int l = 0; l < 128; l++)
            acc = fmaf(__ldg(&w2row[l]), __ldg(&wde[l * 64]), acc);
        g_R[m * 32000 + j * 64 + e] = acc;
        return;
    }
    if (b < 224) {
        __shared__ int sw[16];
        int bid = b - 126;
        int i = bid * 512 + t;
        int v = (i < NN) ? g_degD[i] : 0;
#pragma unroll
        for (int o = 16; o >= 1; o >>= 1) v += __shfl_xor_sync(0xFFFFFFFFu, v, o);
        if ((t & 31) == 0) sw[t >> 5] = v;
        __syncthreads();
        if (t < 32) {
            int x = (t < 16) ? sw[t] : 0;
#pragma unroll
            for (int o = 8; o >= 1; o >>= 1) x += __shfl_xor_sync(0xFFFFFFFFu, x, o);
            if (t == 0) g_bsum[bid] = x;
        }
        return;
    }
    __shared__ float scm[64];
    if (t < 64) {
        int d = t;
        float s = 0.f;
        for (int mm = 0; mm < 2; mm++) {
            float sm = bd[mm * 64 + d];
            for (int l = 0; l < 128; l++)
                sm += g_t2b[mm * 128 + l] * Wd[mm * 8192 + l * 64 + d];
            s += sm;
        }
        scm[d] = 0.5f * s;
    }
    __syncthreads();
    if (t < 64) {
        float s = 0.f;
        for (int d = 0; d < 64; d++) s += scm[d] * Wg0[d * 64 + t];
        g_cprime[t] = s;
    }
}

// ---- L3: MB (blocks 0..499) + scanC (blocks 500..597) -------------------------
__global__ __launch_bounds__(512) void k_MBscan(const float* __restrict__ W1) {
    int b = blockIdx.x;
    int t = threadIdx.x;
    if (b < 500) {
        __shared__ float sA[8][500];
        __shared__ float red[7][8][64];
        int m = b / 250, i0 = (b % 250) * 8;
        for (int idx = t; idx < 4000; idx += 512) {
            int r = idx / 500, j = idx - r * 500;
            sA[r][j] = W1[m * 1000000 + (i0 + r) * 500 + j] * g_alpha1[m * 500 + j];
        }
        __syncthreads();
        int e = t & 63, jp = t >> 6;
        float acc[8] = {0, 0, 0, 0, 0, 0, 0, 0};
        for (int j = jp; j < 500; j += 8) {
            float w = g_R[m * 32000 + j * 64 + e];
#pragma unroll
            for (int r = 0; r < 8; r++) acc[r] += sA[r][j] * w;
        }
        if (jp > 0) {
#pragma unroll
            for (int r = 0; r < 8; r++) red[jp - 1][r][e] = acc[r];
        }
        __syncthreads();
        if (jp == 0) {
#pragma unroll
            for (int r = 0; r < 8; r++) {
                float v = acc[r];
#pragma unroll
                for (int p = 0; p < 7; p++) v += red[p][r][e];
                g_Bhi[e * 4096 + m * 2048 + i0 + r] = __float2half_rn(v * BSCALE);
            }
        }
        return;
    }
    __shared__ int sd[512];
    __shared__ int sboff;
    int bid = b - 500;
    int i = bid * 512 + t;
    int v = (i < NN) ? g_degD[i] : 0;
    sd[t] = v;
    __syncthreads();
    for (int s = 1; s < 512; s <<= 1) {
        int x = (t >= s) ? sd[t - s] : 0;
        __syncthreads();
        sd[t] += x;
        __syncthreads();
    }
    if (t == 0) {
        int run = 0;
        for (int j = 0; j < bid; j++) run += g_bsum[j];
        sboff = run;
        if (bid == 0) g_off[NN] = EE;
    }
    __syncthreads();
    if (i < NN) {
        g_off[i] = sboff + sd[t] - v;
        g_cs[i] = rsqrtf(fmaxf((float)g_degS[i], 1.0f));
        g_cd[i] = rsqrtf(fmaxf((float)v, 1.0f));
    }
}

// ---- L4: 64x64-tile fp16 HMMA GEMM (splitK=2 over m) + fill + rezero ----------
#define SM_A 0                       // 2 buf x 8192 (fp16 A, 64 rows)
#define SM_B 16384                   // 2 buf x 8192 (fp16 B)
#define SMEM_BYTES 32768
#define GEMM_BLKS 1564
#define FILL_BLKS 3125

__global__ __launch_bounds__(128, 4) void k_gemm_hmma(const float* __restrict__ h,
                                                      const int* __restrict__ src,
                                                      const int* __restrict__ dst) {
    int b = blockIdx.x;
    int tid = threadIdx.x;
    if (b >= GEMM_BLKS) {
        if (b < GEMM_BLKS + FILL_BLKS) {
            int e0 = (b - GEMM_BLKS) * 512;
#pragma unroll
            for (int it = 0; it < 4; it++) {
                int e = e0 + it * 128 + tid;
                g_esrc[g_off[dst[e]] + g_epos[e]] = src[e];
            }
        } else {
            int i0 = (b - GEMM_BLKS - FILL_BLKS) * 512;
#pragma unroll
            for (int it = 0; it < 4; it++) {
                int i = i0 + it * 128 + tid;
                if (i < NN) { g_degS[i] = 0; g_degD[i] = 0; }
            }
        }
        return;
    }

    extern __shared__ __align__(1024) char smem[];
    uint32_t sbase = smem_u32(smem);
    int lane = tid & 31, wid = tid >> 5;
    int wm = wid >> 1, wn = wid & 1;
    int bx = b % 782, m = b / 782;
    int row0 = bx * 64;
    const float* hb = h + (long long)m * NN * DINN;
    const __half* bhi = g_Bhi + m * 2048;

    uint32_t swz = (uint32_t)(lane & 7) << 4;
    uint32_t aoff = (uint32_t)(wm * 32 + (lane & 15)) * 128;
    uint32_t acolsel = (uint32_t)(lane >> 4) << 4;
    uint32_t boff = (uint32_t)(wn * 32 + lane) * 128;

    float c_[2][4][4];
#pragma unroll
    for (int mt = 0; mt < 2; mt++)
#pragma unroll
        for (int nt = 0; nt < 4; nt++)
#pragma unroll
            for (int q = 0; q < 4; q++) c_[mt][nt][q] = 0.f;

    float4 va[8];

    auto ldgA = [&](int c) {
        int k0 = c * 64;
        const float* base = hb + (long long)row0 * DINN + k0;
        if (row0 + 64 <= NN && k0 + 64 <= 2000) {
#pragma unroll
            for (int i = 0; i < 8; i++) {
                int idx = tid + 128 * i;
                int r = idx >> 4, cg = idx & 15;
                va[i] = *reinterpret_cast<const float4*>(base + (long long)r * DINN + cg * 4);
            }
        } else {
#pragma unroll
            for (int i = 0; i < 8; i++) {
                int idx = tid + 128 * i;
                int r = idx >> 4, cg = idx & 15;
                if (row0 + r < NN && k0 + cg * 4 + 3 < 2000)
                    va[i] = *reinterpret_cast<const float4*>(base + (long long)r * DINN + cg * 4);
                else
                    va[i] = make_float4(0.f, 0.f, 0.f, 0.f);
            }
        }
    };

    auto cpB = [&](int c, int buf) {
        int k0 = c * 64;
        uint32_t bH = sbase + SM_B + buf * 8192;
#pragma unroll
        for (int i = 0; i < 4; i++) {
            int idx = tid + 128 * i;
            int r = idx >> 3, cg = idx & 7;
            uint32_t off = (uint32_t)r * 128 +
                           (((uint32_t)cg * 16) ^ (((uint32_t)r & 7) << 4));
            CP_ASYNC16(bH + off, bhi + r * 4096 + k0 + cg * 8);
        }
        CP_COMMIT();
    };

    auto stsA = [&](int buf) {
        uint32_t aH = SM_A + buf * 8192;
#pragma unroll
        for (int i = 0; i < 8; i++) {
            int idx = tid + 128 * i;
            int r = idx >> 4, cg = idx & 15;
            float4 v = va[i];
            __half2 h01 = __float22half2_rn(make_float2(v.x, v.y));
            __half2 h23 = __float22half2_rn(make_float2(v.z, v.w));
            uint32_t off = (uint32_t)r * 128 +
                           (((uint32_t)cg * 8) ^ (((uint32_t)r & 7) << 4));
            *reinterpret_cast<uint2*>(smem + aH + off) =
                make_uint2(*reinterpret_cast<uint32_t*>(&h01),
                           *reinterpret_cast<uint32_t*>(&h23));
        }
    };

    auto compute = [&](int buf) {
        uint32_t aH = sbase + SM_A + buf * 8192;
        uint32_t bH = sbase + SM_B + buf * 8192;
#pragma unroll
        for (int ks = 0; ks < 4; ks++) {
            uint32_t kb = (uint32_t)ks * 32;
            uint32_t aF[2][4];
            uint32_t b0h[4], b1h[4];
#pragma unroll
            for (int mt = 0; mt < 2; mt++) {
                uint32_t adr = aoff + (uint32_t)mt * 2048 + ((kb + acolsel) ^ swz);
                LDSM4(aF[mt], aH + adr);
            }
            LDSM4(b0h, bH + boff + ((kb + 0) ^ swz));
            LDSM4(b1h, bH + boff + ((kb + 16) ^ swz));
#pragma unroll
            for (int mt = 0; mt < 2; mt++)
#pragma unroll
                for (int nt = 0; nt < 4; nt++)
                    MMA2(c_[mt][nt], aF[mt], b0h[nt], b1h[nt]);
        }
    };

    ldgA(0);
    cpB(0, 0);
    stsA(0);
    CP_WAIT0();
    __syncthreads();

    for (int c = 0; c < 32; c++) {
        int buf = c & 1;
        bool more = (c + 1 < 32);
        if (more) {
            ldgA(c + 1);
            cpB(c + 1, buf ^ 1);
        }
        compute(buf);
        if (more) {
            stsA(buf ^ 1);
            CP_WAIT0();
            __syncthreads();
        }
    }

    int g = lane >> 2;
    int base_r = row0 + wm * 32 + g;
    int col0 = wn * 32 + (lane & 3) * 2;
#pragma unroll
    for (int mt = 0; mt < 2; mt++) {
#pragma unroll
        for (int rr = 0; rr < 2; rr++) {
            int gr = base_r + mt * 16 + rr * 8;
            if (gr < NN) {
#pragma unroll
                for (int nt = 0; nt < 4; nt++) {
                    int col = col0 + nt * 8;
                    float2 v;
                    v.x = c_[mt][nt][rr * 2 + 0] * BINV;
                    v.y = c_[mt][nt][rr * 2 + 1] * BINV;
                    atomicAdd(reinterpret_cast<float2*>(&g_xw0[gr * 64 + col]), v);
                }
            }
        }
    }
}

// ---- L5: gather cs*(xw0+c') + relu/bias/norm + GEMV 64->32 -> xw1 -------------
__global__ __launch_bounds__(256) void k_g64(const float* __restrict__ bg0,
                                             const float* __restrict__ Wg1) {
    __shared__ float sW[64 * 32];
    __shared__ float sb[64];
    __shared__ float sc[64];
    int t = threadIdx.x;
    for (int i = t; i < 2048; i += 256) sW[i] = Wg1[i];
    if (t < 64) { sb[t] = bg0[t]; sc[t] = g_cprime[t]; }
    __syncthreads();
    int wid = t >> 5, lane = t & 31;
    int n = blockIdx.x * 8 + wid;
    if (n >= NN) return;
    int beg = g_off[n], end = g_off[n + 1];
    int half = lane >> 4, l16 = lane & 15;
    float4 acc = make_float4(0.f, 0.f, 0.f, 0.f);
    float scs = 0.f;
    int i = beg + half;
    while (i + 6 < end) {
        int s0 = __ldg(&g_esrc[i]), s1 = __ldg(&g_esrc[i + 2]);
        int s2 = __ldg(&g_esrc[i + 4]), s3 = __ldg(&g_esrc[i + 6]);
        float cs0 = __ldg(&g_cs[s0]), cs1 = __ldg(&g_cs[s1]);
        float cs2 = __ldg(&g_cs[s2]), cs3 = __ldg(&g_cs[s3]);
        float4 v0 = __ldg(reinterpret_cast<const float4*>(&g_xw0[s0 * 64 + l16 * 4]));
        float4 v1 = __ldg(reinterpret_cast<const float4*>(&g_xw0[s1 * 64 + l16 * 4]));
        float4 v2 = __ldg(reinterpret_cast<const float4*>(&g_xw0[s2 * 64 + l16 * 4]));
        float4 v3 = __ldg(reinterpret_cast<const float4*>(&g_xw0[s3 * 64 + l16 * 4]));
        acc.x += v0.x * cs0 + v1.x * cs1 + v2.x * cs2 + v3.x * cs3;
        acc.y += v0.y * cs0 + v1.y * cs1 + v2.y * cs2 + v3.y * cs3;
        acc.z += v0.z * cs0 + v1.z * cs1 + v2.z * cs2 + v3.z * cs3;
        acc.w += v0.w * cs0 + v1.w * cs1 + v2.w * cs2 + v3.w * cs3;
        scs += cs0 + cs1 + cs2 + cs3;
        i += 8;
    }
    while (i < end) {
        int s = __ldg(&g_esrc[i]);
        float cs0 = __ldg(&g_cs[s]);
        float4 v = __ldg(reinterpret_cast<const float4*>(&g_xw0[s * 64 + l16 * 4]));
        acc.x += v.x * cs0; acc.y += v.y * cs0; acc.z += v.z * cs0; acc.w += v.w * cs0;
        scs += cs0;
        i += 2;
    }
    acc.x += __shfl_xor_sync(0xFFFFFFFFu, acc.x, 16);
    acc.y += __shfl_xor_sync(0xFFFFFFFFu, acc.y, 16);
    acc.z += __shfl_xor_sync(0xFFFFFFFFu, acc.z, 16);
    acc.w += __shfl_xor_sync(0xFFFFFFFFu, acc.w, 16);
    scs   += __shfl_xor_sync(0xFFFFFFFFu, scs, 16);
    float cdv = g_cd[n], csv = g_cs[n];
    float val[4];
    val[0] = fmaxf(fmaf(fmaf(sc[l16 * 4 + 0], scs, acc.x), cdv, sb[l16 * 4 + 0]), 0.f) * csv;
    val[1] = fmaxf(fmaf(fmaf(sc[l16 * 4 + 1], scs, acc.y), cdv, sb[l16 * 4 + 1]), 0.f) * csv;
    val[2] = fmaxf(fmaf(fmaf(sc[l16 * 4 + 2], scs, acc.z), cdv, sb[l16 * 4 + 2]), 0.f) * csv;
    val[3] = fmaxf(fmaf(fmaf(sc[l16 * 4 + 3], scs, acc.w), cdv, sb[l16 * 4 + 3]), 0.f) * csv;
    float o = 0.f;
#pragma unroll
    for (int d = 0; d < 64; d++) {
        float v = __shfl_sync(0xFFFFFFFFu, val[d & 3], d >> 2);
        o = fmaf(v, sW[d * 32 + lane], o);
    }
    g_xw1[n * 32 + lane] = o;
}

// ---- L6: gather xw1 + relu/bias/norm + GEMV 32->4 -> xw2 ----------------------
__global__ __launch_bounds__(256) void k_g32(const float* __restrict__ bg1,
                                             const float* __restrict__ Wg2) {
    __shared__ float sW[32 * 4];
    __shared__ float sb[32];
    int t = threadIdx.x;
    if (t < 128) sW[t] = Wg2[t];
    if (t < 32) sb[t] = bg1[t];
    __syncthreads();
    int wid = t >> 5, lane = t & 31;
    int n = blockIdx.x * 8 + wid;
    if (n >= NN) return;
    int beg = g_off[n], end = g_off[n + 1];
    int q = lane >> 3, l8 = lane & 7;
    float4 acc = make_float4(0.f, 0.f, 0.f, 0.f);
    int i = beg + q;
    while (i + 12 < end) {
        int s0 = __ldg(&g_esrc[i]), s1 = __ldg(&g_esrc[i + 4]);
        int s2 = __ldg(&g_esrc[i + 8]), s3 = __ldg(&g_esrc[i + 12]);
        float4 v0 = __ldg(reinterpret_cast<const float4*>(&g_xw1[s0 * 32 + l8 * 4]));
        float4 v1 = __ldg(reinterpret_cast<const float4*>(&g_xw1[s1 * 32 + l8 * 4]));
        float4 v2 = __ldg(reinterpret_cast<const float4*>(&g_xw1[s2 * 32 + l8 * 4]));
        float4 v3 = __ldg(reinterpret_cast<const float4*>(&g_xw1[s3 * 32 + l8 * 4]));
        acc.x += v0.x + v1.x + v2.x + v3.x;
        acc.y += v0.y + v1.y + v2.y + v3.y;
        acc.z += v0.z + v1.z + v2.z + v3.z;
        acc.w += v0.w + v1.w + v2.w + v3.w;
        i += 16;
    }
    while (i < end) {
        int s = __ldg(&g_esrc[i]);
        float4 v = __ldg(reinterpret_cast<const float4*>(&g_xw1[s * 32 + l8 * 4]));
        acc.x += v.x; acc.y += v.y; acc.z += v.z; acc.w += v.w;
        i += 4;
    }
    acc.x += __shfl_xor_sync(0xFFFFFFFFu, acc.x, 8);
    acc.y += __shfl_xor_sync(0xFFFFFFFFu, acc.y, 8);
    acc.z += __shfl_xor_sync(0xFFFFFFFFu, acc.z, 8);
    acc.w += __shfl_xor_sync(0xFFFFFFFFu, acc.w, 8);
    acc.x += __shfl_xor_sync(0xFFFFFFFFu, acc.x, 16);
    acc.y += __shfl_xor_sync(0xFFFFFFFFu, acc.y, 16);
    acc.z += __shfl_xor_sync(0xFFFFFFFFu, acc.z, 16);
    acc.w += __shfl_xor_sync(0xFFFFFFFFu, acc.w, 16);
    float cdv = g_cd[n], csv = g_cs[n];
    float val[4];
    val[0] = fmaxf(fmaf(acc.x, cdv, sb[l8 * 4 + 0]), 0.f) * csv;
    val[1] = fmaxf(fmaf(acc.y, cdv, sb[l8 * 4 + 1]), 0.f) * csv;
    val[2] = fmaxf(fmaf(acc.z, cdv, sb[l8 * 4 + 2]), 0.f) * csv;
    val[3] = fmaxf(fmaf(acc.w, cdv, sb[l8 * 4 + 3]), 0.f) * csv;
    float o = 0.f;
#pragma unroll
    for (int d = 0; d < 32; d++) {
        float v = __shfl_sync(0xFFFFFFFFu, val[d & 3], d >> 2);
        o = fmaf(v, sW[d * 4 + (lane & 3)], o);
    }
    if (lane < 4) g_xw2[n * 4 + lane] = o;
}

// ---- L7: gather xw2 + bias -> out ---------------------------------------------
__global__ __launch_bounds__(256) void k_g4(const float* __restrict__ bg2,
                                            float* __restrict__ out) {
    int t = threadIdx.x;
    int wid = t >> 5, lane = t & 31;
    int n = blockIdx.x * 8 + wid;
    if (n >= NN) return;
    int beg = g_off[n], end = g_off[n + 1];
    float4 acc = make_float4(0.f, 0.f, 0.f, 0.f);
    for (int i = beg + lane; i < end; i += 32) {
        int s = __ldg(&g_esrc[i]);
        float4 v = __ldg(reinterpret_cast<const float4*>(&g_xw2[s * 4]));
        acc.x += v.x; acc.y += v.y; acc.z += v.z; acc.w += v.w;
    }
#pragma unroll
    for (int off = 16; off >= 1; off >>= 1) {
        acc.x += __shfl_xor_sync(0xFFFFFFFFu, acc.x, off);
        acc.y += __shfl_xor_sync(0xFFFFFFFFu, acc.y, off);
        acc.z += __shfl_xor_sync(0xFFFFFFFFu, acc.z, off);
        acc.w += __shfl_xor_sync(0xFFFFFFFFu, acc.w, off);
    }
    if (lane == 0) {
        float cdv = g_cd[n];
        float4 o;
        o.x = fmaf(acc.x, cdv, bg2[0]);
        o.y = fmaf(acc.y, cdv, bg2[1]);
        o.z = fmaf(acc.z, cdv, bg2[2]);
        o.w = fmaf(acc.w, cdv, bg2[3]);
        *reinterpret_cast<float4*>(&out[n * 4]) = o;
    }
}

// ---------------- launch ----------------
extern "C" void kernel_launch(void* const* d_in, const int* in_sizes, int n_in,
                              void* d_out, int out_size) {
    const float* h   = (const float*)d_in[0];
    const int*   src = (const int*)d_in[1];
    const int*   dst = (const int*)d_in[2];
    const float* W1  = (const float*)d_in[3];
    const float* b1  = (const float*)d_in[4];
    const float* g1  = (const float*)d_in[5];
    const float* be1 = (const float*)d_in[6];
    const float* m1  = (const float*)d_in[7];
    const float* v1  = (const float*)d_in[8];
    const float* W2  = (const float*)d_in[9];
    const float* b2  = (const float*)d_in[10];
    const float* g2  = (const float*)d_in[11];
    const float* be2 = (const float*)d_in[12];
    const float* m2  = (const float*)d_in[13];
    const float* v2  = (const float*)d_in[14];
    const float* Wd  = (const float*)d_in[15];
    const float* bd  = (const float*)d_in[16];
    const float* Wg0 = (const float*)d_in[17];
    const float* bg0 = (const float*)d_in[18];
    const float* Wg1 = (const float*)d_in[19];
    const float* bg1 = (const float*)d_in[20];
    const float* Wg2 = (const float*)d_in[21];
    const float* bg2 = (const float*)d_in[22];
    float* out = (float*)d_out;

    cudaFuncSetAttribute(k_gemm_hmma, cudaFuncAttributeMaxDynamicSharedMemorySize,
                         SMEM_BYTES);

    k_fold<<<3358, 512>>>(src, dst, b1, g1, be1, m1, v1, W2, b2, g2,   // 1
                          be2, m2, v2, Wd, bd, Wg0);
    k_Rscan<<<225, 512>>>(W2, Wd, bd, Wg0);                            // 2
    k_MBscan<<<598, 512>>>(W1);                                        // 3
    k_gemm_hmma<<<GEMM_BLKS + FILL_BLKS + 98, 128, SMEM_BYTES>>>(h, src, dst);  // 4 <- ncu
    k_g64<<<(NN + 7) / 8, 256>>>(bg0, Wg1);                            // 5
    k_g32<<<(NN + 7) / 8, 256>>>(bg1, Wg2);                            // 6
    k_g4<<<(NN + 7) / 8, 256>>>(bg2, out);                             // 7
}

// round 15
// speedup vs baseline: 1.2684x; 1.0005x over previous
#include <cuda_runtime.h>
#include <cuda_fp16.h>
#include <cstdint>

#define NN   50000
#define EE   1600000
#define DINN 2000
#define BSCALE 4096.0f
#define BINV   (1.0f / 4096.0f)

// ---------------- device scratch (allocation-free contract) ----------------
__device__ float g_alpha1[2 * 500];
__device__ float g_t2b[2 * 128];
__device__ float g_cprime[64];
__device__ float g_Wde2[2 * 128 * 64];   // 0.5 * alpha2[l] * (Wd @ Wg0)
__device__ float g_R[2 * 500 * 64];      // W2 @ Wde2
__device__ __half g_Bhi[64 * 4096];      // [e][m*2048+k] fp16 of 4096*M^T (pad zero)
__device__ float g_xw0[NN * 64];         // fp32 splitK accumulation target
__device__ float g_xw1[NN * 32];
__device__ float g_xw2[NN * 4];
__device__ float g_cs[NN];
__device__ float g_cd[NN];
__device__ int   g_degS[NN];             // zero at load; re-zeroed each call
__device__ int   g_degD[NN];
__device__ int   g_off[NN + 1];
__device__ int   g_epos[EE];
__device__ int   g_esrc[EE];
__device__ int   g_bsum[128];

// ---------------- PTX helpers ----------------
__device__ __forceinline__ uint32_t smem_u32(const void* p) {
    uint32_t a;
    asm("{ .reg .u64 t; cvta.to.shared.u64 t, %1; cvt.u32.u64 %0, t; }"
        : "=r"(a) : "l"(p));
    return a;
}

#define LDSM4(r, a) \
    asm volatile("ldmatrix.sync.aligned.m8n8.x4.shared.b16 {%0,%1,%2,%3}, [%4];" \
                 : "=r"((r)[0]), "=r"((r)[1]), "=r"((r)[2]), "=r"((r)[3]) : "r"(a))

#define MMA2(c, a, b0, b1) \
    asm volatile( \
        "mma.sync.aligned.m16n8k16.row.col.f32.f16.f16.f32 " \
        "{%0,%1,%2,%3}, {%4,%5,%6,%7}, {%8,%9}, {%0,%1,%2,%3};" \
        : "+f"((c)[0]), "+f"((c)[1]), "+f"((c)[2]), "+f"((c)[3]) \
        : "r"((a)[0]), "r"((a)[1]), "r"((a)[2]), "r"((a)[3]), \
          "r"(b0), "r"(b1))

#define CP_ASYNC16(dst, src) \
    asm volatile("cp.async.cg.shared.global [%0], [%1], 16;" \
                 :: "r"(dst), "l"(src) : "memory")
#define CP_COMMIT() asm volatile("cp.async.commit_group;" ::: "memory")
#define CP_WAIT0()  asm volatile("cp.async.wait_group 0;" ::: "memory")

// ---- L1: Wde2 (blk 0..31) + t2b (blk 32) + edges (33..3157) + zero (3158..) ---
__global__ __launch_bounds__(512) void k_fold(
    const int* __restrict__ src, const int* __restrict__ dst,
    const float* __restrict__ b1, const float* __restrict__ g1,
    const float* __restrict__ be1, const float* __restrict__ m1,
    const float* __restrict__ v1, const float* __restrict__ W2,
    const float* __restrict__ b2, const float* __restrict__ g2,
    const float* __restrict__ be2, const float* __restrict__ m2,
    const float* __restrict__ v2, const float* __restrict__ Wd,
    const float* __restrict__ bd, const float* __restrict__ Wg0) {
    int b = blockIdx.x;
    int t = threadIdx.x;
    if (b < 32) {
        int idx = b * 512 + t;
        int m = idx >> 13, l = (idx >> 6) & 127, e = idx & 63;
        float a2 = g2[m * 128 + l] * rsqrtf(v2[m * 128 + l] + 1e-5f);
        const float* wdrow = Wd + m * 8192 + l * 64;
        float s = 0.f;
#pragma unroll 4
        for (int d = 0; d < 64; d++)
            s = fmaf(__ldg(&wdrow[d]), __ldg(&Wg0[d * 64 + e]), s);
        g_Wde2[idx] = 0.5f * a2 * s;
        return;
    }
    if (b == 32) {
        __shared__ float sbb1[1000];
        for (int i = t; i < 1000; i += 512) {
            float a = g1[i] * rsqrtf(v1[i] + 1e-5f);
            g_alpha1[i] = a;
            sbb1[i] = (b1[i] - m1[i]) * a + be1[i];
        }
        __syncthreads();
        if (t < 256) {
            int mm = t >> 7, l = t & 127;
            float s = 0.f;
            for (int j = 0; j < 500; j++)
                s += sbb1[mm * 500 + j] * W2[mm * 64000 + j * 128 + l];
            float a2 = g2[t] * rsqrtf(v2[t] + 1e-5f);
            g_t2b[t] = (s + b2[t] - m2[t]) * a2 + be2[t];
        }
        return;
    }
    if (b < 33 + 3125) {
        int e = (b - 33) * 512 + t;
        if (e < EE) {
            g_epos[e] = atomicAdd(&g_degD[dst[e]], 1);
            atomicAdd(&g_degS[src[e]], 1);
        }
        return;
    }
    float4 z = make_float4(0.f, 0.f, 0.f, 0.f);
    for (int i = (b - 3158) * 512 + t; i < NN * 16; i += 200 * 512)
        reinterpret_cast<float4*>(g_xw0)[i] = z;
}

// ---- L2: R (blk 0..125) + scanA (126..223) + cprime (224) ---------------------
__global__ __launch_bounds__(512) void k_Rscan(const float* __restrict__ W2,
                                               const float* __restrict__ Wd,
                                               const float* __restrict__ bd,
                                               const float* __restrict__ Wg0) {
    int b = blockIdx.x;
    int t = threadIdx.x;
    if (b < 126) {
        int m = b / 63, j0 = (b % 63) * 8;
        int jr = t >> 6, e = t & 63;
        int j = j0 + jr;
        if (j >= 500) return;
        const float* w2row = W2 + m * 64000 + j * 128;
        const float* wde = g_Wde2 + m * 8192 + e;
        float acc = 0.f;
#pragma unroll 4
        for (int l = 0; l < 128; l++)
            acc = fmaf(__ldg(&w2row[l]), __ldg(&wde[l * 64]), acc);
        g_R[m * 32000 + j * 64 + e] = acc;
        return;
    }
    if (b < 224) {
        __shared__ int sw[16];
        int bid = b - 126;
        int i = bid * 512 + t;
        int v = (i < NN) ? g_degD[i] : 0;
#pragma unroll
        for (int o = 16; o >= 1; o >>= 1) v += __shfl_xor_sync(0xFFFFFFFFu, v, o);
        if ((t & 31) == 0) sw[t >> 5] = v;
        __syncthreads();
        if (t < 32) {
            int x = (t < 16) ? sw[t] : 0;
#pragma unroll
            for (int o = 8; o >= 1; o >>= 1) x += __shfl_xor_sync(0xFFFFFFFFu, x, o);
            if (t == 0) g_bsum[bid] = x;
        }
        return;
    }
    __shared__ float scm[64];
    if (t < 64) {
        int d = t;
        float s = 0.f;
        for (int mm = 0; mm < 2; mm++) {
            float sm = bd[mm * 64 + d];
            for (int l = 0; l < 128; l++)
                sm += g_t2b[mm * 128 + l] * Wd[mm * 8192 + l * 64 + d];
            s += sm;
        }
        scm[d] = 0.5f * s;
    }
    __syncthreads();
    if (t < 64) {
        float s = 0.f;
        for (int d = 0; d < 64; d++) s += scm[d] * Wg0[d * 64 + t];
        g_cprime[t] = s;
    }
}

// ---- L3: MB (blocks 0..499) + scanC (blocks 500..597) -------------------------
__global__ __launch_bounds__(512) void k_MBscan(const float* __restrict__ W1) {
    int b = blockIdx.x;
    int t = threadIdx.x;
    if (b < 500) {
        __shared__ float sA[8][500];
        __shared__ float red[7][8][64];
        int m = b / 250, i0 = (b % 250) * 8;
        for (int idx = t; idx < 4000; idx += 512) {
            int r = idx / 500, j = idx - r * 500;
            sA[r][j] = W1[m * 1000000 + (i0 + r) * 500 + j] * g_alpha1[m * 500 + j];
        }
        __syncthreads();
        int e = t & 63, jp = t >> 6;
        float acc[8] = {0, 0, 0, 0, 0, 0, 0, 0};
        for (int j = jp; j < 500; j += 8) {
            float w = g_R[m * 32000 + j * 64 + e];
#pragma unroll
            for (int r = 0; r < 8; r++) acc[r] += sA[r][j] * w;
        }
        if (jp > 0) {
#pragma unroll
            for (int r = 0; r < 8; r++) red[jp - 1][r][e] = acc[r];
        }
        __syncthreads();
        if (jp == 0) {
#pragma unroll
            for (int r = 0; r < 8; r++) {
                float v = acc[r];
#pragma unroll
                for (int p = 0; p < 7; p++) v += red[p][r][e];
                g_Bhi[e * 4096 + m * 2048 + i0 + r] = __float2half_rn(v * BSCALE);
            }
        }
        return;
    }
    __shared__ int sd[512];
    __shared__ int sboff;
    int bid = b - 500;
    int i = bid * 512 + t;
    int v = (i < NN) ? g_degD[i] : 0;
    sd[t] = v;
    __syncthreads();
    for (int s = 1; s < 512; s <<= 1) {
        int x = (t >= s) ? sd[t - s] : 0;
        __syncthreads();
        sd[t] += x;
        __syncthreads();
    }
    if (t == 0) {
        int run = 0;
        for (int j = 0; j < bid; j++) run += g_bsum[j];
        sboff = run;
        if (bid == 0) g_off[NN] = EE;
    }
    __syncthreads();
    if (i < NN) {
        g_off[i] = sboff + sd[t] - v;
        g_cs[i] = rsqrtf(fmaxf((float)g_degS[i], 1.0f));
        g_cd[i] = rsqrtf(fmaxf((float)v, 1.0f));
    }
}

// ---- L4: 64x64-tile fp16 HMMA GEMM (splitK=2 over m) + fill + rezero ----------
#define SM_A 0                       // 2 buf x 8192 (fp16 A, 64 rows)
#define SM_B 16384                   // 2 buf x 8192 (fp16 B)
#define SMEM_BYTES 32768
#define GEMM_BLKS 1564
#define FILL_BLKS 3125

__global__ __launch_bounds__(128, 4) void k_gemm_hmma(const float* __restrict__ h,
                                                      const int* __restrict__ src,
                                                      const int* __restrict__ dst) {
    int b = blockIdx.x;
    int tid = threadIdx.x;
    if (b >= GEMM_BLKS) {
        if (b < GEMM_BLKS + FILL_BLKS) {
            int e0 = (b - GEMM_BLKS) * 512;
#pragma unroll
            for (int it = 0; it < 4; it++) {
                int e = e0 + it * 128 + tid;
                g_esrc[g_off[dst[e]] + g_epos[e]] = src[e];
            }
        } else {
            int i0 = (b - GEMM_BLKS - FILL_BLKS) * 512;
#pragma unroll
            for (int it = 0; it < 4; it++) {
                int i = i0 + it * 128 + tid;
                if (i < NN) { g_degS[i] = 0; g_degD[i] = 0; }
            }
        }
        return;
    }

    extern __shared__ __align__(1024) char smem[];
    uint32_t sbase = smem_u32(smem);
    int lane = tid & 31, wid = tid >> 5;
    int wm = wid >> 1, wn = wid & 1;
    int bx = b % 782, m = b / 782;
    int row0 = bx * 64;
    const float* hb = h + (long long)m * NN * DINN;
    const __half* bhi = g_Bhi + m * 2048;

    uint32_t swz = (uint32_t)(lane & 7) << 4;
    uint32_t aoff = (uint32_t)(wm * 32 + (lane & 15)) * 128;
    uint32_t acolsel = (uint32_t)(lane >> 4) << 4;
    uint32_t boff = (uint32_t)(wn * 32 + lane) * 128;

    float c_[2][4][4];
#pragma unroll
    for (int mt = 0; mt < 2; mt++)
#pragma unroll
        for (int nt = 0; nt < 4; nt++)
#pragma unroll
            for (int q = 0; q < 4; q++) c_[mt][nt][q] = 0.f;

    float4 va[8];

    auto ldgA = [&](int c) {
        int k0 = c * 64;
        const float* base = hb + (long long)row0 * DINN + k0;
        if (row0 + 64 <= NN && k0 + 64 <= 2000) {
#pragma unroll
            for (int i = 0; i < 8; i++) {
                int idx = tid + 128 * i;
                int r = idx >> 4, cg = idx & 15;
                va[i] = *reinterpret_cast<const float4*>(base + (long long)r * DINN + cg * 4);
            }
        } else {
#pragma unroll
            for (int i = 0; i < 8; i++) {
                int idx = tid + 128 * i;
                int r = idx >> 4, cg = idx & 15;
                if (row0 + r < NN && k0 + cg * 4 + 3 < 2000)
                    va[i] = *reinterpret_cast<const float4*>(base + (long long)r * DINN + cg * 4);
                else
                    va[i] = make_float4(0.f, 0.f, 0.f, 0.f);
            }
        }
    };

    auto cpB = [&](int c, int buf) {
        int k0 = c * 64;
        uint32_t bH = sbase + SM_B + buf * 8192;
#pragma unroll
        for (int i = 0; i < 4; i++) {
            int idx = tid + 128 * i;
            int r = idx >> 3, cg = idx & 7;
            uint32_t off = (uint32_t)r * 128 +
                           (((uint32_t)cg * 16) ^ (((uint32_t)r & 7) << 4));
            CP_ASYNC16(bH + off, bhi + r * 4096 + k0 + cg * 8);
        }
        CP_COMMIT();
    };

    auto stsA = [&](int buf) {
        uint32_t aH = SM_A + buf * 8192;
#pragma unroll
        for (int i = 0; i < 8; i++) {
            int idx = tid + 128 * i;
            int r = idx >> 4, cg = idx & 15;
            float4 v = va[i];
            __half2 h01 = __float22half2_rn(make_float2(v.x, v.y));
            __half2 h23 = __float22half2_rn(make_float2(v.z, v.w));
            uint32_t off = (uint32_t)r * 128 +
                           (((uint32_t)cg * 8) ^ (((uint32_t)r & 7) << 4));
            *reinterpret_cast<uint2*>(smem + aH + off) =
                make_uint2(*reinterpret_cast<uint32_t*>(&h01),
                           *reinterpret_cast<uint32_t*>(&h23));
        }
    };

    auto compute = [&](int buf) {
        uint32_t aH = sbase + SM_A + buf * 8192;
        uint32_t bH = sbase + SM_B + buf * 8192;
#pragma unroll
        for (int ks = 0; ks < 4; ks++) {
            uint32_t kb = (uint32_t)ks * 32;
            uint32_t aF[2][4];
            uint32_t b0h[4], b1h[4];
#pragma unroll
            for (int mt = 0; mt < 2; mt++) {
                uint32_t adr = aoff + (uint32_t)mt * 2048 + ((kb + acolsel) ^ swz);
                LDSM4(aF[mt], aH + adr);
            }
            LDSM4(b0h, bH + boff + ((kb + 0) ^ swz));
            LDSM4(b1h, bH + boff + ((kb + 16) ^ swz));
#pragma unroll
            for (int mt = 0; mt < 2; mt++)
#pragma unroll
                for (int nt = 0; nt < 4; nt++)
                    MMA2(c_[mt][nt], aF[mt], b0h[nt], b1h[nt]);
        }
    };

    ldgA(0);
    cpB(0, 0);
    stsA(0);
    CP_WAIT0();
    __syncthreads();

    for (int c = 0; c < 32; c++) {
        int buf = c & 1;
        bool more = (c + 1 < 32);
        if (more) {
            ldgA(c + 1);
            cpB(c + 1, buf ^ 1);
        }
        compute(buf);
        if (more) {
            stsA(buf ^ 1);
            CP_WAIT0();
            __syncthreads();
        }
    }

    int g = lane >> 2;
    int base_r = row0 + wm * 32 + g;
    int col0 = wn * 32 + (lane & 3) * 2;
#pragma unroll
    for (int mt = 0; mt < 2; mt++) {
#pragma unroll
        for (int rr = 0; rr < 2; rr++) {
            int gr = base_r + mt * 16 + rr * 8;
            if (gr < NN) {
#pragma unroll
                for (int nt = 0; nt < 4; nt++) {
                    int col = col0 + nt * 8;
                    float2 v;
                    v.x = c_[mt][nt][rr * 2 + 0] * BINV;
                    v.y = c_[mt][nt][rr * 2 + 1] * BINV;
                    atomicAdd(reinterpret_cast<float2*>(&g_xw0[gr * 64 + col]), v);
                }
            }
        }
    }
}

// ---- L5: gather cs*(xw0+c') + relu/bias/norm + GEMV 64->32 -> xw1 -------------
__global__ __launch_bounds__(256) void k_g64(const float* __restrict__ bg0,
                                             const float* __restrict__ Wg1) {
    __shared__ float sW[64 * 32];
    __shared__ float sb[64];
    __shared__ float sc[64];
    int t = threadIdx.x;
    for (int i = t; i < 2048; i += 256) sW[i] = Wg1[i];
    if (t < 64) { sb[t] = bg0[t]; sc[t] = g_cprime[t]; }
    __syncthreads();
    int wid = t >> 5, lane = t & 31;
    int n = blockIdx.x * 8 + wid;
    if (n >= NN) return;
    int beg = g_off[n], end = g_off[n + 1];
    int half = lane >> 4, l16 = lane & 15;
    float4 acc = make_float4(0.f, 0.f, 0.f, 0.f);
    float scs = 0.f;
    int i = beg + half;
    while (i + 6 < end) {
        int s0 = __ldg(&g_esrc[i]), s1 = __ldg(&g_esrc[i + 2]);
        int s2 = __ldg(&g_esrc[i + 4]), s3 = __ldg(&g_esrc[i + 6]);
        float cs0 = __ldg(&g_cs[s0]), cs1 = __ldg(&g_cs[s1]);
        float cs2 = __ldg(&g_cs[s2]), cs3 = __ldg(&g_cs[s3]);
        float4 v0 = __ldg(reinterpret_cast<const float4*>(&g_xw0[s0 * 64 + l16 * 4]));
        float4 v1 = __ldg(reinterpret_cast<const float4*>(&g_xw0[s1 * 64 + l16 * 4]));
        float4 v2 = __ldg(reinterpret_cast<const float4*>(&g_xw0[s2 * 64 + l16 * 4]));
        float4 v3 = __ldg(reinterpret_cast<const float4*>(&g_xw0[s3 * 64 + l16 * 4]));
        acc.x += v0.x * cs0 + v1.x * cs1 + v2.x * cs2 + v3.x * cs3;
        acc.y += v0.y * cs0 + v1.y * cs1 + v2.y * cs2 + v3.y * cs3;
        acc.z += v0.z * cs0 + v1.z * cs1 + v2.z * cs2 + v3.z * cs3;
        acc.w += v0.w * cs0 + v1.w * cs1 + v2.w * cs2 + v3.w * cs3;
        scs += cs0 + cs1 + cs2 + cs3;
        i += 8;
    }
    while (i < end) {
        int s = __ldg(&g_esrc[i]);
        float cs0 = __ldg(&g_cs[s]);
        float4 v = __ldg(reinterpret_cast<const float4*>(&g_xw0[s * 64 + l16 * 4]));
        acc.x += v.x * cs0; acc.y += v.y * cs0; acc.z += v.z * cs0; acc.w += v.w * cs0;
        scs += cs0;
        i += 2;
    }
    acc.x += __shfl_xor_sync(0xFFFFFFFFu, acc.x, 16);
    acc.y += __shfl_xor_sync(0xFFFFFFFFu, acc.y, 16);
    acc.z += __shfl_xor_sync(0xFFFFFFFFu, acc.z, 16);
    acc.w += __shfl_xor_sync(0xFFFFFFFFu, acc.w, 16);
    scs   += __shfl_xor_sync(0xFFFFFFFFu, scs, 16);
    float cdv = g_cd[n], csv = g_cs[n];
    float val[4];
    val[0] = fmaxf(fmaf(fmaf(sc[l16 * 4 + 0], scs, acc.x), cdv, sb[l16 * 4 + 0]), 0.f) * csv;
    val[1] = fmaxf(fmaf(fmaf(sc[l16 * 4 + 1], scs, acc.y), cdv, sb[l16 * 4 + 1]), 0.f) * csv;
    val[2] = fmaxf(fmaf(fmaf(sc[l16 * 4 + 2], scs, acc.z), cdv, sb[l16 * 4 + 2]), 0.f) * csv;
    val[3] = fmaxf(fmaf(fmaf(sc[l16 * 4 + 3], scs, acc.w), cdv, sb[l16 * 4 + 3]), 0.f) * csv;
    float o = 0.f;
#pragma unroll
    for (int d = 0; d < 64; d++) {
        float v = __shfl_sync(0xFFFFFFFFu, val[d & 3], d >> 2);
        o = fmaf(v, sW[d * 32 + lane], o);
    }
    g_xw1[n * 32 + lane] = o;
}

// ---- L6: gather xw1 + relu/bias/norm + GEMV 32->4 -> xw2 ----------------------
__global__ __launch_bounds__(256) void k_g32(const float* __restrict__ bg1,
                                             const float* __restrict__ Wg2) {
    __shared__ float sW[32 * 4];
    __shared__ float sb[32];
    int t = threadIdx.x;
    if (t < 128) sW[t] = Wg2[t];
    if (t < 32) sb[t] = bg1[t];
    __syncthreads();
    int wid = t >> 5, lane = t & 31;
    int n = blockIdx.x * 8 + wid;
    if (n >= NN) return;
    int beg = g_off[n], end = g_off[n + 1];
    int q = lane >> 3, l8 = lane & 7;
    float4 acc = make_float4(0.f, 0.f, 0.f, 0.f);
    int i = beg + q;
    while (i + 12 < end) {
        int s0 = __ldg(&g_esrc[i]), s1 = __ldg(&g_esrc[i + 4]);
        int s2 = __ldg(&g_esrc[i + 8]), s3 = __ldg(&g_esrc[i + 12]);
        float4 v0 = __ldg(reinterpret_cast<const float4*>(&g_xw1[s0 * 32 + l8 * 4]));
        float4 v1 = __ldg(reinterpret_cast<const float4*>(&g_xw1[s1 * 32 + l8 * 4]));
        float4 v2 = __ldg(reinterpret_cast<const float4*>(&g_xw1[s2 * 32 + l8 * 4]));
        float4 v3 = __ldg(reinterpret_cast<const float4*>(&g_xw1[s3 * 32 + l8 * 4]));
        acc.x += v0.x + v1.x + v2.x + v3.x;
        acc.y += v0.y + v1.y + v2.y + v3.y;
        acc.z += v0.z + v1.z + v2.z + v3.z;
        acc.w += v0.w + v1.w + v2.w + v3.w;
        i += 16;
    }
    while (i < end) {
        int s = __ldg(&g_esrc[i]);
        float4 v = __ldg(reinterpret_cast<const float4*>(&g_xw1[s * 32 + l8 * 4]));
        acc.x += v.x; acc.y += v.y; acc.z += v.z; acc.w += v.w;
        i += 4;
    }
    acc.x += __shfl_xor_sync(0xFFFFFFFFu, acc.x, 8);
    acc.y += __shfl_xor_sync(0xFFFFFFFFu, acc.y, 8);
    acc.z += __shfl_xor_sync(0xFFFFFFFFu, acc.z, 8);
    acc.w += __shfl_xor_sync(0xFFFFFFFFu, acc.w, 8);
    acc.x += __shfl_xor_sync(0xFFFFFFFFu, acc.x, 16);
    acc.y += __shfl_xor_sync(0xFFFFFFFFu, acc.y, 16);
    acc.z += __shfl_xor_sync(0xFFFFFFFFu, acc.z, 16);
    acc.w += __shfl_xor_sync(0xFFFFFFFFu, acc.w, 16);
    float cdv = g_cd[n], csv = g_cs[n];
    float val[4];
    val[0] = fmaxf(fmaf(acc.x, cdv, sb[l8 * 4 + 0]), 0.f) * csv;
    val[1] = fmaxf(fmaf(acc.y, cdv, sb[l8 * 4 + 1]), 0.f) * csv;
    val[2] = fmaxf(fmaf(acc.z, cdv, sb[l8 * 4 + 2]), 0.f) * csv;
    val[3] = fmaxf(fmaf(acc.w, cdv, sb[l8 * 4 + 3]), 0.f) * csv;
    float o = 0.f;
#pragma unroll
    for (int d = 0; d < 32; d++) {
        float v = __shfl_sync(0xFFFFFFFFu, val[d & 3], d >> 2);
        o = fmaf(v, sW[d * 4 + (lane & 3)], o);
    }
    if (lane < 4) g_xw2[n * 4 + lane] = o;
}

// ---- L7: gather xw2 + bias -> out ---------------------------------------------
__global__ __launch_bounds__(256) void k_g4(const float* __restrict__ bg2,
                                            float* __restrict__ out) {
    int t = threadIdx.x;
    int wid = t >> 5, lane = t & 31;
    int n = blockIdx.x * 8 + wid;
    if (n >= NN) return;
    int beg = g_off[n], end = g_off[n + 1];
    float4 acc = make_float4(0.f, 0.f, 0.f, 0.f);
    for (int i = beg + lane; i < end; i += 32) {
        int s = __ldg(&g_esrc[i]);
        float4 v = __ldg(reinterpret_cast<const float4*>(&g_xw2[s * 4]));
        acc.x += v.x; acc.y += v.y; acc.z += v.z; acc.w += v.w;
    }
#pragma unroll
    for (int off = 16; off >= 1; off >>= 1) {
        acc.x += __shfl_xor_sync(0xFFFFFFFFu, acc.x, off);
        acc.y += __shfl_xor_sync(0xFFFFFFFFu, acc.y, off);
        acc.z += __shfl_xor_sync(0xFFFFFFFFu, acc.z, off);
        acc.w += __shfl_xor_sync(0xFFFFFFFFu, acc.w, off);
    }
    if (lane == 0) {
        float cdv = g_cd[n];
        float4 o;
        o.x = fmaf(acc.x, cdv, bg2[0]);
        o.y = fmaf(acc.y, cdv, bg2[1]);
        o.z = fmaf(acc.z, cdv, bg2[2]);
        o.w = fmaf(acc.w, cdv, bg2[3]);
        *reinterpret_cast<float4*>(&out[n * 4]) = o;
    }
}

// ---------------- launch ----------------
extern "C" void kernel_launch(void* const* d_in, const int* in_sizes, int n_in,
                              void* d_out, int out_size) {
    const float* h   = (const float*)d_in[0];
    const int*   src = (const int*)d_in[1];
    const int*   dst = (const int*)d_in[2];
    const float* W1  = (const float*)d_in[3];
    const float* b1  = (const float*)d_in[4];
    const float* g1  = (const float*)d_in[5];
    const float* be1 = (const float*)d_in[6];
    const float* m1  = (const float*)d_in[7];
    const float* v1  = (const float*)d_in[8];
    const float* W2  = (const float*)d_in[9];
    const float* b2  = (const float*)d_in[10];
    const float* g2  = (const float*)d_in[11];
    const float* be2 = (const float*)d_in[12];
    const float* m2  = (const float*)d_in[13];
    const float* v2  = (const float*)d_in[14];
    const float* Wd  = (const float*)d_in[15];
    const float* bd  = (const float*)d_in[16];
    const float* Wg0 = (const float*)d_in[17];
    const float* bg0 = (const float*)d_in[18];
    const float* Wg1 = (const float*)d_in[19];
    const float* bg1 = (const float*)d_in[20];
    const float* Wg2 = (const float*)d_in[21];
    const float* bg2 = (const float*)d_in[22];
    float* out = (float*)d_out;

    cudaFuncSetAttribute(k_gemm_hmma, cudaFuncAttributeMaxDynamicSharedMemorySize,
                         SMEM_BYTES);

    k_fold<<<3358, 512>>>(src, dst, b1, g1, be1, m1, v1, W2, b2, g2,   // 1
                          be2, m2, v2, Wd, bd, Wg0);
    k_Rscan<<<225, 512>>>(W2, Wd, bd, Wg0);                            // 2
    k_MBscan<<<598, 512>>>(W1);                                        // 3
    k_gemm_hmma<<<GEMM_BLKS + FILL_BLKS + 98, 128, SMEM_BYTES>>>(h, src, dst);  // 4 <- ncu
    k_g64<<<(NN + 7) / 8, 256>>>(bg0, Wg1);                            // 5
    k_g32<<<(NN + 7) / 8, 256>>>(bg1, Wg2);                            // 6
    k_g4<<<(NN + 7) / 8, 256>>>(bg2, out);                             // 7
}